// round 3
// baseline (speedup 1.0000x reference)
#include <cuda_runtime.h>
#include <cuda_bf16.h>
#include <mma.h>
#include <math.h>

using namespace nvcuda;

#define Bsz  256
#define Tsz  128
#define Hsz  1024
#define G3   3072
#define Vsz  348
#define Vpad 384
#define Kd   1024
#define NBLK 148
#define WSEG 3145728   // 3072*1024

// ---------------- scratch (device globals; no allocs allowed) ----------------
__device__ float          g_gi1[(size_t)Tsz * Bsz * G3];   // precomputed layer-1 input gates (no bias)
__device__ __nv_bfloat16  g_xb[(size_t)Tsz * Bsz * Kd];    // gathered embeddings, bf16
__device__ __nv_bfloat16  g_wb[6 * (size_t)WSEG];          // [w_ih1,w_hh1,w_ih2,w_hh2,w_ih3,w_hh3] bf16
__device__ __nv_bfloat16  g_wout[Vpad * Kd];               // padded w_out bf16 (rows 348..383 = 0)
__device__ float          g_gi[Bsz * G3];
__device__ float          g_gh[Bsz * G3];
__device__ float          g_h1[Bsz * Hsz], g_h2[Bsz * Hsz], g_h3[Bsz * Hsz];
__device__ __nv_bfloat16  g_h1b[Bsz * Hsz], g_h2b[Bsz * Hsz], g_h3b[Bsz * Hsz];
__device__ float          g_logits[Bsz * Vpad];
__device__ unsigned       g_bar_count;
__device__ volatile unsigned g_bar_gen;

namespace {
struct Boot {
    Boot() { void* p = nullptr; cudaGetSymbolAddress(&p, g_gi1); }
};
static Boot boot_;
}

// ---------------- software grid barrier (all 148 blocks co-resident) ----------------
__device__ __forceinline__ void grid_barrier(unsigned& gen) {
    __syncthreads();
    __threadfence();                       // every thread publishes its writes
    if (threadIdx.x == 0) {
        unsigned arr = atomicAdd(&g_bar_count, 1u);
        if (arr == gridDim.x - 1) {
            g_bar_count = 0u;
            __threadfence();
            g_bar_gen = gen + 1;           // release
        } else {
            while (g_bar_gen == gen) { }   // volatile spin (L2-coherent)
        }
        __threadfence();
    }
    gen++;
    __syncthreads();
}

// ---------------- bf16 wmma GEMM unit: C[64x64] = A[64xK] @ W[64xK]^T ----------------
// A, W bf16 row-major with ld = 1024 (K). C fp32 row-major ld = ldC. No bias.
// Block = 256 threads = 8 warps; warp w -> m-tile (w&3), n-pair (w>>2).
__device__ __forceinline__ void gemm_unit(
    const __nv_bfloat16* __restrict__ A,
    const __nv_bfloat16* __restrict__ W,
    float* __restrict__ C, int ldC,
    int m0, int n0,
    __nv_bfloat16* As, __nv_bfloat16* Bs)
{
    const int tid  = threadIdx.x;
    const int warp = tid >> 5;
    const int mw   = warp & 3;
    const int np   = warp >> 2;            // 0 or 1

    wmma::fragment<wmma::accumulator, 16, 16, 16, float> acc0, acc1;
    wmma::fill_fragment(acc0, 0.f);
    wmma::fill_fragment(acc1, 0.f);

    const int lrow = tid >> 2;             // 0..63
    const int lk   = (tid & 3) << 3;       // 0,8,16,24
    const __nv_bfloat16* gA = A + (size_t)(m0 + lrow) * Kd + lk;
    const __nv_bfloat16* gW = W + (size_t)(n0 + lrow) * Kd + lk;
    __nv_bfloat16* sa = As + lrow * 40 + lk;
    __nv_bfloat16* sb = Bs + lrow * 40 + lk;

    float4 ra = *(const float4*)gA;
    float4 rb = *(const float4*)gW;

    #pragma unroll 1
    for (int c = 0; c < Kd / 32; c++) {
        *(float4*)sa = ra;
        *(float4*)sb = rb;
        __syncthreads();
        if (c < Kd / 32 - 1) {             // prefetch next chunk while mma runs
            ra = *(const float4*)(gA + (c + 1) * 32);
            rb = *(const float4*)(gW + (c + 1) * 32);
        }
        #pragma unroll
        for (int ks = 0; ks < 2; ks++) {
            wmma::fragment<wmma::matrix_a, 16, 16, 16, __nv_bfloat16, wmma::row_major> af;
            wmma::fragment<wmma::matrix_b, 16, 16, 16, __nv_bfloat16, wmma::col_major> bf0, bf1;
            wmma::load_matrix_sync(af,  As + mw * 16 * 40 + ks * 16, 40);
            wmma::load_matrix_sync(bf0, Bs + (np * 32 +  0) * 40 + ks * 16, 40);
            wmma::load_matrix_sync(bf1, Bs + (np * 32 + 16) * 40 + ks * 16, 40);
            wmma::mma_sync(acc0, af, bf0, acc0);
            wmma::mma_sync(acc1, af, bf1, acc1);
        }
        __syncthreads();
    }
    wmma::store_matrix_sync(C + (size_t)(m0 + mw * 16) * ldC + n0 + np * 32,      acc0, ldC, wmma::mem_row_major);
    wmma::store_matrix_sync(C + (size_t)(m0 + mw * 16) * ldC + n0 + np * 32 + 16, acc1, ldC, wmma::mem_row_major);
}

// ---------------- phase helpers (run inside persistent kernel) ----------------
__device__ __forceinline__ float sigmoidf_(float x) { return 1.f / (1.f + __expf(-x)); }

__device__ __forceinline__ void gate_phase(
    const float* __restrict__ gi, const float* __restrict__ gh,
    const float* __restrict__ bi, const float* __restrict__ bh,
    float* __restrict__ h, __nv_bfloat16* __restrict__ hb)
{
    for (int idx = blockIdx.x * blockDim.x + threadIdx.x;
         idx < Bsz * Hsz; idx += gridDim.x * blockDim.x) {
        int b = idx >> 10, j = idx & 1023;
        const float* gib = gi + (size_t)b * G3;
        const float* ghb = gh + (size_t)b * G3;
        float r  = sigmoidf_(gib[j]        + bi[j]        + ghb[j]        + bh[j]);
        float z  = sigmoidf_(gib[1024 + j] + bi[1024 + j] + ghb[1024 + j] + bh[1024 + j]);
        float n  = tanhf(gib[2048 + j] + bi[2048 + j] + r * (ghb[2048 + j] + bh[2048 + j]));
        float hv = (1.f - z) * n + z * h[idx];
        h[idx]  = hv;
        hb[idx] = __float2bfloat16(hv);
    }
}

__device__ __forceinline__ void logprob_phase(
    int t, const int* __restrict__ target, const float* __restrict__ b_out,
    float* __restrict__ lp, float* red)
{
    for (int b = blockIdx.x; b < Bsz; b += gridDim.x) {
        const float* row = g_logits + (size_t)b * Vpad;
        int tid = threadIdx.x;
        float m = -1e30f;
        for (int v = tid; v < Vsz; v += 256) m = fmaxf(m, row[v] + b_out[v]);
        red[tid] = m; __syncthreads();
        for (int s = 128; s; s >>= 1) { if (tid < s) red[tid] = fmaxf(red[tid], red[tid + s]); __syncthreads(); }
        float mx = red[0]; __syncthreads();
        float sacc = 0.f;
        for (int v = tid; v < Vsz; v += 256) sacc += __expf(row[v] + b_out[v] - mx);
        red[tid] = sacc; __syncthreads();
        for (int s = 128; s; s >>= 1) { if (tid < s) red[tid] += red[tid + s]; __syncthreads(); }
        if (tid == 0) {
            int tg = target[b * Tsz + t];
            lp[b] += row[tg] + b_out[tg] - (mx + __logf(red[0]));
        }
        __syncthreads();
    }
}

// ---------------- persistent recurrence kernel ----------------
__global__ __launch_bounds__(256, 1) void recur_kernel(
    const int* __restrict__ target,
    const float* __restrict__ b_ih1, const float* __restrict__ b_hh1,
    const float* __restrict__ b_ih2, const float* __restrict__ b_hh2,
    const float* __restrict__ b_ih3, const float* __restrict__ b_hh3,
    const float* __restrict__ b_out,
    float* __restrict__ lp)
{
    __shared__ __align__(16) __nv_bfloat16 As[64 * 40];
    __shared__ __align__(16) __nv_bfloat16 Bs[64 * 40];
    __shared__ float red[256];
    unsigned gen = 0;

    for (int t = 0; t < Tsz; t++) {
        // gh1 = h1 @ w_hh1^T  (192 units of 64x64 over 256x3072)
        for (int u = blockIdx.x; u < 192; u += gridDim.x)
            gemm_unit(g_h1b, g_wb + 1 * (size_t)WSEG, g_gh, G3, (u / 48) * 64, (u % 48) * 64, As, Bs);
        grid_barrier(gen);
        gate_phase(g_gi1 + (size_t)t * Bsz * G3, g_gh, b_ih1, b_hh1, g_h1, g_h1b);
        grid_barrier(gen);

        // gi2 = h1 @ w_ih2^T ; gh2 = h2 @ w_hh2^T  (384 units)
        for (int u = blockIdx.x; u < 384; u += gridDim.x) {
            if (u < 192) gemm_unit(g_h1b, g_wb + 2 * (size_t)WSEG, g_gi, G3, (u / 48) * 64, (u % 48) * 64, As, Bs);
            else { int v = u - 192;
                   gemm_unit(g_h2b, g_wb + 3 * (size_t)WSEG, g_gh, G3, (v / 48) * 64, (v % 48) * 64, As, Bs); }
        }
        grid_barrier(gen);
        gate_phase(g_gi, g_gh, b_ih2, b_hh2, g_h2, g_h2b);
        grid_barrier(gen);

        // gi3 = h2 @ w_ih3^T ; gh3 = h3 @ w_hh3^T
        for (int u = blockIdx.x; u < 384; u += gridDim.x) {
            if (u < 192) gemm_unit(g_h2b, g_wb + 4 * (size_t)WSEG, g_gi, G3, (u / 48) * 64, (u % 48) * 64, As, Bs);
            else { int v = u - 192;
                   gemm_unit(g_h3b, g_wb + 5 * (size_t)WSEG, g_gh, G3, (v / 48) * 64, (v % 48) * 64, As, Bs); }
        }
        grid_barrier(gen);
        gate_phase(g_gi, g_gh, b_ih3, b_hh3, g_h3, g_h3b);
        grid_barrier(gen);

        // logits = h3 @ w_out^T  (24 units of 64x64 over 256x384)
        for (int u = blockIdx.x; u < 24; u += gridDim.x)
            gemm_unit(g_h3b, g_wout, g_logits, Vpad, (u / 6) * 64, (u % 6) * 64, As, Bs);
        grid_barrier(gen);
        logprob_phase(t, target, b_out, lp, red);
        // no barrier needed: next phase that touches g_logits is 6 barriers away
    }
}

// ---------------- setup kernels ----------------
__global__ __launch_bounds__(256) void init_state(float* lp) {
    for (int i = blockIdx.x * blockDim.x + threadIdx.x;
         i < Bsz * Hsz; i += gridDim.x * blockDim.x) {
        g_h1[i] = 0.f; g_h2[i] = 0.f; g_h3[i] = 0.f;
        __nv_bfloat16 z = __float2bfloat16(0.f);
        g_h1b[i] = z; g_h2b[i] = z; g_h3b[i] = z;
        if (i < Bsz) lp[i] = 0.f;
        if (i == 0) { g_bar_count = 0u; g_bar_gen = 0u; }
    }
}

__global__ __launch_bounds__(256) void conv_weights(
    const float* __restrict__ w0, const float* __restrict__ w1,
    const float* __restrict__ w2, const float* __restrict__ w3,
    const float* __restrict__ w4, const float* __restrict__ w5)
{
    for (size_t i = (size_t)blockIdx.x * blockDim.x + threadIdx.x;
         i < 6 * (size_t)WSEG; i += (size_t)gridDim.x * blockDim.x) {
        int seg = (int)(i / WSEG);
        size_t off = i % WSEG;
        const float* s = seg == 0 ? w0 : seg == 1 ? w1 : seg == 2 ? w2
                       : seg == 3 ? w3 : seg == 4 ? w4 : w5;
        g_wb[i] = __float2bfloat16(s[off]);
    }
}

__global__ __launch_bounds__(256) void conv_wout(const float* __restrict__ w_out) {
    for (int i = blockIdx.x * blockDim.x + threadIdx.x;
         i < Vpad * Kd; i += gridDim.x * blockDim.x) {
        int row = i >> 10;
        g_wout[i] = (row < Vsz) ? __float2bfloat16(w_out[i]) : __float2bfloat16(0.f);
    }
}

__global__ __launch_bounds__(256) void gather_x(
    const int* __restrict__ target, const int* __restrict__ bosp,
    const float* __restrict__ emb)
{
    // one float4 (4 elems) per iteration
    const int nq = Tsz * Bsz * (Kd / 4);
    for (int i = blockIdx.x * blockDim.x + threadIdx.x; i < nq; i += gridDim.x * blockDim.x) {
        int m  = i / (Kd / 4);
        int kq = i % (Kd / 4);
        int t = m >> 8, b = m & 255;
        int tok = (t == 0) ? bosp[0] : target[(b << 7) + t - 1];
        float4 v = *(const float4*)(emb + (size_t)tok * Kd + kq * 4);
        __nv_bfloat16* dst = g_xb + (size_t)m * Kd + kq * 4;
        *(__nv_bfloat162*)(dst)     = __floats2bfloat162_rn(v.x, v.y);
        *(__nv_bfloat162*)(dst + 2) = __floats2bfloat162_rn(v.z, v.w);
    }
}

__global__ __launch_bounds__(256) void gemm_gi1_kernel() {
    __shared__ __align__(16) __nv_bfloat16 As[64 * 40];
    __shared__ __align__(16) __nv_bfloat16 Bs[64 * 40];
    gemm_unit(g_xb, g_wb /* w_ih1 */, g_gi1, G3,
              blockIdx.y * 64, blockIdx.x * 64, As, Bs);
}

// ---------------- launch ----------------
extern "C" void kernel_launch(void* const* d_in, const int* in_sizes, int n_in,
                              void* d_out, int out_size)
{
    (void)in_sizes; (void)n_in; (void)out_size;
    const int*   target = (const int*)  d_in[0];
    const int*   bos    = (const int*)  d_in[1];
    const float* emb    = (const float*)d_in[2];
    const float* w_ih1  = (const float*)d_in[3];
    const float* w_hh1  = (const float*)d_in[4];
    const float* b_ih1  = (const float*)d_in[5];
    const float* b_hh1  = (const float*)d_in[6];
    const float* w_ih2  = (const float*)d_in[7];
    const float* w_hh2  = (const float*)d_in[8];
    const float* b_ih2  = (const float*)d_in[9];
    const float* b_hh2  = (const float*)d_in[10];
    const float* w_ih3  = (const float*)d_in[11];
    const float* w_hh3  = (const float*)d_in[12];
    const float* b_ih3  = (const float*)d_in[13];
    const float* b_hh3  = (const float*)d_in[14];
    const float* w_out  = (const float*)d_in[15];
    const float* b_out  = (const float*)d_in[16];
    float* lp = (float*)d_out;

    init_state<<<1024, 256>>>(lp);
    conv_weights<<<8192, 256>>>(w_ih1, w_hh1, w_ih2, w_hh2, w_ih3, w_hh3);
    conv_wout<<<(Vpad * Kd + 255) / 256, 256>>>(w_out);
    gather_x<<<8192, 256>>>(target, bos, emb);

    {
        dim3 grid(G3 / 64, (Tsz * Bsz) / 64);   // 48 x 512
        gemm_gi1_kernel<<<grid, 256>>>();
    }

    recur_kernel<<<NBLK, 256>>>(target,
                                b_ih1, b_hh1, b_ih2, b_hh2, b_ih3, b_hh3,
                                b_out, lp);
}

// round 4
// speedup vs baseline: 1.1085x; 1.1085x over previous
#include <cuda_runtime.h>
#include <cuda_bf16.h>
#include <mma.h>
#include <math.h>

using namespace nvcuda;

#define Bsz  256
#define Tsz  128
#define Hsz  1024
#define G3   3072
#define Vsz  348
#define Vpad 384
#define Kd   1024
#define NBLK 148
#define WSEG 3145728   // 3072*1024

// GEMM tile config: 128(m) x 64(n), K chunk 64, smem row stride 72 halfs (144B)
#define TM   128
#define TN   64
#define KC   64
#define SST  72
#define SMEM_GEMM ((2*TM*SST + 2*TN*SST) * 2)   // 55296 bytes

// ---------------- scratch (device globals; no allocs allowed) ----------------
__device__ float          g_gi1[(size_t)Tsz * Bsz * G3];
__device__ __nv_bfloat16  g_xb[(size_t)Tsz * Bsz * Kd];
__device__ __nv_bfloat16  g_wb[6 * (size_t)WSEG];
__device__ __nv_bfloat16  g_wout[Vpad * Kd];
__device__ float          g_gi[Bsz * G3];
__device__ float          g_gh[Bsz * G3];
__device__ float          g_h1[Bsz * Hsz], g_h2[Bsz * Hsz], g_h3[Bsz * Hsz];
__device__ __nv_bfloat16  g_h1b[Bsz * Hsz], g_h2b[Bsz * Hsz], g_h3b[Bsz * Hsz];
__device__ float          g_logits[Bsz * Vpad];
__device__ unsigned       g_bar_count;
__device__ volatile unsigned g_bar_gen;

namespace {
struct Boot {
    Boot() { void* p = nullptr; cudaGetSymbolAddress(&p, g_gi1); }
};
static Boot boot_;
}

// ---------------- cp.async helpers ----------------
__device__ __forceinline__ void cpa16(void* smem, const void* gptr) {
    unsigned sa = (unsigned)__cvta_generic_to_shared(smem);
    asm volatile("cp.async.cg.shared.global [%0], [%1], 16;\n" :: "r"(sa), "l"(gptr));
}
__device__ __forceinline__ void cpa_commit() {
    asm volatile("cp.async.commit_group;\n");
}
template <int N>
__device__ __forceinline__ void cpa_wait() {
    asm volatile("cp.async.wait_group %0;\n" :: "n"(N));
}

// ---------------- software grid barrier ----------------
__device__ __forceinline__ void grid_barrier(unsigned& gen) {
    __syncthreads();
    __threadfence();
    if (threadIdx.x == 0) {
        unsigned arr = atomicAdd(&g_bar_count, 1u);
        if (arr == gridDim.x - 1) {
            g_bar_count = 0u;
            __threadfence();
            g_bar_gen = gen + 1;
        } else {
            while (g_bar_gen == gen) { }
        }
        __threadfence();
    }
    gen++;
    __syncthreads();
}

// ---------------- GEMM tile: C[TM x TN] = A[TM x K] @ W[TN x K]^T ----------------
// A, W bf16 row-major ld=Kd. C fp32 row-major ld=ldC. 256 threads = 8 warps (4m x 2n).
// Double-buffered cp.async pipeline over K in chunks of KC=64.
__device__ __forceinline__ void gemm_tile(
    const __nv_bfloat16* __restrict__ A,
    const __nv_bfloat16* __restrict__ W,
    float* __restrict__ C, int ldC,
    int m0, int n0,
    __nv_bfloat16* smem)
{
    __nv_bfloat16* As[2] = { smem,             smem + TM * SST };
    __nv_bfloat16* Ws[2] = { smem + 2*TM*SST,  smem + 2*TM*SST + TN * SST };

    const int tid  = threadIdx.x;
    const int warp = tid >> 5;
    const int mw   = warp & 3;     // 0..3 -> 32-row slab
    const int nw   = warp >> 2;    // 0..1 -> 32-col slab

    // A loads: 128 rows x 8 segs(16B) = 1024 segs, 4 per thread
    const int arow = tid >> 1;
    const int aseg = (tid & 1) * 4;
    // W loads: 64 rows x 8 segs = 512 segs, 2 per thread
    const int wrow = tid >> 2;
    const int wseg = (tid & 3) * 2;

    const __nv_bfloat16* gA = A + (size_t)(m0 + arow) * Kd + aseg * 8;
    const __nv_bfloat16* gW = W + (size_t)(n0 + wrow) * Kd + wseg * 8;
    __nv_bfloat16* saBase[2] = { As[0] + arow * SST + aseg * 8, As[1] + arow * SST + aseg * 8 };
    __nv_bfloat16* swBase[2] = { Ws[0] + wrow * SST + wseg * 8, Ws[1] + wrow * SST + wseg * 8 };

    wmma::fragment<wmma::accumulator, 16, 16, 16, float> acc[2][2];
    #pragma unroll
    for (int i = 0; i < 2; i++)
        #pragma unroll
        for (int j = 0; j < 2; j++) wmma::fill_fragment(acc[i][j], 0.f);

    const int NC = Kd / KC;   // 16

    // prologue: issue chunk 0
    {
        const __nv_bfloat16* a = gA;
        const __nv_bfloat16* w = gW;
        #pragma unroll
        for (int i = 0; i < 4; i++) cpa16(saBase[0] + i * 8, a + i * 8);
        #pragma unroll
        for (int i = 0; i < 2; i++) cpa16(swBase[0] + i * 8, w + i * 8);
        cpa_commit();
    }

    #pragma unroll 1
    for (int c = 0; c < NC; c++) {
        if (c + 1 < NC) {
            int nb = (c + 1) & 1;
            const __nv_bfloat16* a = gA + (c + 1) * KC;
            const __nv_bfloat16* w = gW + (c + 1) * KC;
            #pragma unroll
            for (int i = 0; i < 4; i++) cpa16(saBase[nb] + i * 8, a + i * 8);
            #pragma unroll
            for (int i = 0; i < 2; i++) cpa16(swBase[nb] + i * 8, w + i * 8);
            cpa_commit();
            cpa_wait<1>();
        } else {
            cpa_wait<0>();
        }
        __syncthreads();

        const __nv_bfloat16* sa = As[c & 1];
        const __nv_bfloat16* sw = Ws[c & 1];
        #pragma unroll
        for (int ks = 0; ks < KC / 16; ks++) {
            wmma::fragment<wmma::matrix_a, 16, 16, 16, __nv_bfloat16, wmma::row_major> a0, a1;
            wmma::fragment<wmma::matrix_b, 16, 16, 16, __nv_bfloat16, wmma::col_major> b0, b1;
            wmma::load_matrix_sync(a0, sa + (mw * 32 +  0) * SST + ks * 16, SST);
            wmma::load_matrix_sync(a1, sa + (mw * 32 + 16) * SST + ks * 16, SST);
            wmma::load_matrix_sync(b0, sw + (nw * 32 +  0) * SST + ks * 16, SST);
            wmma::load_matrix_sync(b1, sw + (nw * 32 + 16) * SST + ks * 16, SST);
            wmma::mma_sync(acc[0][0], a0, b0, acc[0][0]);
            wmma::mma_sync(acc[0][1], a0, b1, acc[0][1]);
            wmma::mma_sync(acc[1][0], a1, b0, acc[1][0]);
            wmma::mma_sync(acc[1][1], a1, b1, acc[1][1]);
        }
        __syncthreads();
    }

    #pragma unroll
    for (int i = 0; i < 2; i++)
        #pragma unroll
        for (int j = 0; j < 2; j++)
            wmma::store_matrix_sync(
                C + (size_t)(m0 + mw * 32 + i * 16) * ldC + n0 + nw * 32 + j * 16,
                acc[i][j], ldC, wmma::mem_row_major);
}

// ---------------- phase helpers ----------------
__device__ __forceinline__ float sigmoidf_(float x) { return 1.f / (1.f + __expf(-x)); }

__device__ __forceinline__ void gate_phase(
    const float* __restrict__ gi, const float* __restrict__ gh,
    const float* __restrict__ bi, const float* __restrict__ bh,
    float* __restrict__ h, __nv_bfloat16* __restrict__ hb)
{
    for (int idx = blockIdx.x * blockDim.x + threadIdx.x;
         idx < Bsz * Hsz; idx += gridDim.x * blockDim.x) {
        int b = idx >> 10, j = idx & 1023;
        const float* gib = gi + (size_t)b * G3;
        const float* ghb = gh + (size_t)b * G3;
        float r  = sigmoidf_(gib[j]        + bi[j]        + ghb[j]        + bh[j]);
        float z  = sigmoidf_(gib[1024 + j] + bi[1024 + j] + ghb[1024 + j] + bh[1024 + j]);
        float n  = tanhf(gib[2048 + j] + bi[2048 + j] + r * (ghb[2048 + j] + bh[2048 + j]));
        float hv = (1.f - z) * n + z * h[idx];
        h[idx]  = hv;
        hb[idx] = __float2bfloat16(hv);
    }
}

__device__ __forceinline__ void logprob_phase(
    int t, const int* __restrict__ target, const float* __restrict__ b_out,
    float* __restrict__ lp, float* red)
{
    for (int b = blockIdx.x; b < Bsz; b += gridDim.x) {
        const float* row = g_logits + (size_t)b * Vpad;
        int tid = threadIdx.x;
        float m = -1e30f;
        for (int v = tid; v < Vsz; v += 256) m = fmaxf(m, row[v] + b_out[v]);
        red[tid] = m; __syncthreads();
        for (int s = 128; s; s >>= 1) { if (tid < s) red[tid] = fmaxf(red[tid], red[tid + s]); __syncthreads(); }
        float mx = red[0]; __syncthreads();
        float sacc = 0.f;
        for (int v = tid; v < Vsz; v += 256) sacc += __expf(row[v] + b_out[v] - mx);
        red[tid] = sacc; __syncthreads();
        for (int s = 128; s; s >>= 1) { if (tid < s) red[tid] += red[tid + s]; __syncthreads(); }
        if (tid == 0) {
            int tg = target[b * Tsz + t];
            lp[b] += row[tg] + b_out[tg] - (mx + __logf(red[0]));
        }
        __syncthreads();
    }
}

// ---------------- persistent recurrence kernel ----------------
__global__ __launch_bounds__(256, 1) void recur_kernel(
    const int* __restrict__ target,
    const float* __restrict__ b_ih1, const float* __restrict__ b_hh1,
    const float* __restrict__ b_ih2, const float* __restrict__ b_hh2,
    const float* __restrict__ b_ih3, const float* __restrict__ b_hh3,
    const float* __restrict__ b_out,
    float* __restrict__ lp)
{
    extern __shared__ __align__(16) __nv_bfloat16 smem[];
    __shared__ float red[256];
    unsigned gen = 0;

    // unit grids: big GEMM (256x3072): 2 m-tiles x 48 n-tiles = 96 units
    for (int t = 0; t < Tsz; t++) {
        // PH1: gh1 = h1 @ w_hh1^T  (96 units)
        for (int u = blockIdx.x; u < 96; u += gridDim.x)
            gemm_tile(g_h1b, g_wb + 1 * (size_t)WSEG, g_gh, G3,
                      (u / 48) * TM, (u % 48) * TN, smem);
        grid_barrier(gen);
        gate_phase(g_gi1 + (size_t)t * Bsz * G3, g_gh, b_ih1, b_hh1, g_h1, g_h1b);
        grid_barrier(gen);

        // PH2: gi2 = h1 @ w_ih2^T ; gh2 = h2 @ w_hh2^T  (192 units)
        for (int u = blockIdx.x; u < 192; u += gridDim.x) {
            if (u < 96) gemm_tile(g_h1b, g_wb + 2 * (size_t)WSEG, g_gi, G3,
                                  (u / 48) * TM, (u % 48) * TN, smem);
            else { int v = u - 96;
                   gemm_tile(g_h2b, g_wb + 3 * (size_t)WSEG, g_gh, G3,
                             (v / 48) * TM, (v % 48) * TN, smem); }
        }
        grid_barrier(gen);
        gate_phase(g_gi, g_gh, b_ih2, b_hh2, g_h2, g_h2b);
        grid_barrier(gen);

        // PH3: gi3 = h2 @ w_ih3^T ; gh3 = h3 @ w_hh3^T
        for (int u = blockIdx.x; u < 192; u += gridDim.x) {
            if (u < 96) gemm_tile(g_h2b, g_wb + 4 * (size_t)WSEG, g_gi, G3,
                                  (u / 48) * TM, (u % 48) * TN, smem);
            else { int v = u - 96;
                   gemm_tile(g_h3b, g_wb + 5 * (size_t)WSEG, g_gh, G3,
                             (v / 48) * TM, (v % 48) * TN, smem); }
        }
        grid_barrier(gen);
        gate_phase(g_gi, g_gh, b_ih3, b_hh3, g_h3, g_h3b);
        grid_barrier(gen);

        // PH4: logits = h3 @ w_out^T  (2 x 6 = 12 units over 256 x 384)
        for (int u = blockIdx.x; u < 12; u += gridDim.x)
            gemm_tile(g_h3b, g_wout, g_logits, Vpad,
                      (u / 6) * TM, (u % 6) * TN, smem);
        grid_barrier(gen);
        logprob_phase(t, target, b_out, lp, red);
        // g_logits next touched 6 barriers from now; no extra barrier needed
    }
}

// ---------------- setup kernels ----------------
__global__ __launch_bounds__(256) void init_state(float* lp) {
    for (int i = blockIdx.x * blockDim.x + threadIdx.x;
         i < Bsz * Hsz; i += gridDim.x * blockDim.x) {
        g_h1[i] = 0.f; g_h2[i] = 0.f; g_h3[i] = 0.f;
        __nv_bfloat16 z = __float2bfloat16(0.f);
        g_h1b[i] = z; g_h2b[i] = z; g_h3b[i] = z;
        if (i < Bsz) lp[i] = 0.f;
        if (i == 0) { g_bar_count = 0u; g_bar_gen = 0u; }
    }
}

__global__ __launch_bounds__(256) void conv_weights(
    const float* __restrict__ w0, const float* __restrict__ w1,
    const float* __restrict__ w2, const float* __restrict__ w3,
    const float* __restrict__ w4, const float* __restrict__ w5)
{
    for (size_t i = (size_t)blockIdx.x * blockDim.x + threadIdx.x;
         i < 6 * (size_t)WSEG; i += (size_t)gridDim.x * blockDim.x) {
        int seg = (int)(i / WSEG);
        size_t off = i % WSEG;
        const float* s = seg == 0 ? w0 : seg == 1 ? w1 : seg == 2 ? w2
                       : seg == 3 ? w3 : seg == 4 ? w4 : w5;
        g_wb[i] = __float2bfloat16(s[off]);
    }
}

__global__ __launch_bounds__(256) void conv_wout(const float* __restrict__ w_out) {
    for (int i = blockIdx.x * blockDim.x + threadIdx.x;
         i < Vpad * Kd; i += gridDim.x * blockDim.x) {
        int row = i >> 10;
        g_wout[i] = (row < Vsz) ? __float2bfloat16(w_out[i]) : __float2bfloat16(0.f);
    }
}

__global__ __launch_bounds__(256) void gather_x(
    const int* __restrict__ target, const int* __restrict__ bosp,
    const float* __restrict__ emb)
{
    const int nq = Tsz * Bsz * (Kd / 4);
    for (int i = blockIdx.x * blockDim.x + threadIdx.x; i < nq; i += gridDim.x * blockDim.x) {
        int m  = i / (Kd / 4);
        int kq = i % (Kd / 4);
        int t = m >> 8, b = m & 255;
        int tok = (t == 0) ? bosp[0] : target[(b << 7) + t - 1];
        float4 v = *(const float4*)(emb + (size_t)tok * Kd + kq * 4);
        __nv_bfloat16* dst = g_xb + (size_t)m * Kd + kq * 4;
        *(__nv_bfloat162*)(dst)     = __floats2bfloat162_rn(v.x, v.y);
        *(__nv_bfloat162*)(dst + 2) = __floats2bfloat162_rn(v.z, v.w);
    }
}

__global__ __launch_bounds__(256, 1) void gemm_gi1_kernel() {
    extern __shared__ __align__(16) __nv_bfloat16 smem[];
    gemm_tile(g_xb, g_wb /* w_ih1 */, g_gi1, G3,
              blockIdx.y * TM, blockIdx.x * TN, smem);
}

// ---------------- launch ----------------
extern "C" void kernel_launch(void* const* d_in, const int* in_sizes, int n_in,
                              void* d_out, int out_size)
{
    (void)in_sizes; (void)n_in; (void)out_size;
    const int*   target = (const int*)  d_in[0];
    const int*   bos    = (const int*)  d_in[1];
    const float* emb    = (const float*)d_in[2];
    const float* w_ih1  = (const float*)d_in[3];
    const float* w_hh1  = (const float*)d_in[4];
    const float* b_ih1  = (const float*)d_in[5];
    const float* b_hh1  = (const float*)d_in[6];
    const float* w_ih2  = (const float*)d_in[7];
    const float* w_hh2  = (const float*)d_in[8];
    const float* b_ih2  = (const float*)d_in[9];
    const float* b_hh2  = (const float*)d_in[10];
    const float* w_ih3  = (const float*)d_in[11];
    const float* w_hh3  = (const float*)d_in[12];
    const float* b_ih3  = (const float*)d_in[13];
    const float* b_hh3  = (const float*)d_in[14];
    const float* w_out  = (const float*)d_in[15];
    const float* b_out  = (const float*)d_in[16];
    float* lp = (float*)d_out;

    cudaFuncSetAttribute(recur_kernel,
        cudaFuncAttributeMaxDynamicSharedMemorySize, SMEM_GEMM);
    cudaFuncSetAttribute(gemm_gi1_kernel,
        cudaFuncAttributeMaxDynamicSharedMemorySize, SMEM_GEMM);

    init_state<<<1024, 256>>>(lp);
    conv_weights<<<8192, 256>>>(w_ih1, w_hh1, w_ih2, w_hh2, w_ih3, w_hh3);
    conv_wout<<<(Vpad * Kd + 255) / 256, 256>>>(w_out);
    gather_x<<<8192, 256>>>(target, bos, emb);

    {
        dim3 grid(G3 / TN, (Tsz * Bsz) / TM);   // 48 x 256
        gemm_gi1_kernel<<<grid, 256, SMEM_GEMM>>>();
    }

    recur_kernel<<<NBLK, 256, SMEM_GEMM>>>(target,
                                b_ih1, b_hh1, b_ih2, b_hh2, b_ih3, b_hh3,
                                b_out, lp);
}

// round 6
// speedup vs baseline: 2.8193x; 2.5432x over previous
#include <cuda_runtime.h>
#include <cuda_bf16.h>
#include <math.h>
#include <stdint.h>

#define Bsz  256
#define Tsz  128
#define Hsz  1024
#define G3   3072
#define Vsz  348
#define Vpad 384
#define Kd   1024
#define NBLK 148
#define WSEG 3145728   // 3072*1024

// GEMM config: BM=256 (=full M), BN=128, BK=32, 256 threads, warp tile 64x64
#define BM 256
#define BN 128
#define PITCH 80                         // smem row pitch bytes (32 bf16 + pad)
#define STAGE_BYTES ((BM + BN) * PITCH)  // 30720
#define NSTAGE 4
#define SMEM_DYN (NSTAGE * STAGE_BYTES + 256)

// ---------------- scratch (device globals; no allocs allowed) ----------------
__device__ float          g_gi1[(size_t)Tsz * Bsz * G3];
__device__ __nv_bfloat16  g_xb[(size_t)Tsz * Bsz * Kd];
__device__ __nv_bfloat16  g_wb[6 * (size_t)WSEG];
__device__ __nv_bfloat16  g_wout[Vpad * Kd];
__device__ float          g_gh1[Bsz * G3];
__device__ float          g_gi2[Bsz * G3], g_gh2[Bsz * G3];
__device__ float          g_gi3[Bsz * G3], g_gh3[Bsz * G3];
__device__ float          g_h1[Bsz * Hsz], g_h2[Bsz * Hsz], g_h3[Bsz * Hsz];
__device__ __nv_bfloat16  g_h1b[Bsz * Hsz], g_h2b[Bsz * Hsz], g_h3b[Bsz * Hsz];
__device__ float          g_logits[Bsz * Vpad];
__device__ unsigned       g_bar_count;   // monotonic
__device__ unsigned       g_bar_gen;     // monotonic

namespace {
struct Boot {
    Boot() { void* p = nullptr; cudaGetSymbolAddress(&p, g_gi1); }
};
static Boot boot_;
}

// ---------------- low-level helpers ----------------
__device__ __forceinline__ uint32_t smem_u32(const void* p) {
    return (uint32_t)__cvta_generic_to_shared(p);
}
__device__ __forceinline__ void cpa16s(uint32_t saddr, const void* g) {
    asm volatile("cp.async.cg.shared.global [%0], [%1], 16;" :: "r"(saddr), "l"(g));
}
__device__ __forceinline__ void cpa_commit() {
    asm volatile("cp.async.commit_group;");
}
template <int N>
__device__ __forceinline__ void cpa_wait() {
    asm volatile("cp.async.wait_group %0;" :: "n"(N));
}
__device__ __forceinline__ void ldsm_x4(uint32_t* r, uint32_t a) {
    asm volatile("ldmatrix.sync.aligned.m8n8.x4.shared.b16 {%0,%1,%2,%3}, [%4];"
        : "=r"(r[0]), "=r"(r[1]), "=r"(r[2]), "=r"(r[3]) : "r"(a));
}
__device__ __forceinline__ void mma16816(float* c, const uint32_t* a, uint32_t b0, uint32_t b1) {
    asm volatile(
        "mma.sync.aligned.m16n8k16.row.col.f32.bf16.bf16.f32 "
        "{%0,%1,%2,%3},{%4,%5,%6,%7},{%8,%9},{%0,%1,%2,%3};"
        : "+f"(c[0]), "+f"(c[1]), "+f"(c[2]), "+f"(c[3])
        : "r"(a[0]), "r"(a[1]), "r"(a[2]), "r"(a[3]), "r"(b0), "r"(b1));
}

// ---------------- grid barrier (release/acquire, monotonic) ----------------
__device__ __forceinline__ void grid_barrier(unsigned& gen) {
    __syncthreads();
    if (threadIdx.x == 0) {
        unsigned target = gen + 1;
        unsigned old;
        asm volatile("atom.add.acq_rel.gpu.u32 %0, [%1], 1;"
                     : "=r"(old) : "l"(&g_bar_count) : "memory");
        if (old == target * NBLK - 1) {
            asm volatile("st.release.gpu.u32 [%0], %1;"
                         :: "l"(&g_bar_gen), "r"(target) : "memory");
        } else {
            unsigned cur;
            do {
                asm volatile("ld.acquire.gpu.u32 %0, [%1];"
                             : "=r"(cur) : "l"(&g_bar_gen) : "memory");
            } while (cur < target);
        }
    }
    gen++;
    __syncthreads();
}

// ---------------- mma.sync GEMM unit: C[256 x 128] = A[256xK] @ W[128xK]^T ----------------
// A bf16 [M][K] row-major; W bf16 [N][K] row-major (= B col-major for mma.row.col).
// 256 threads = 8 warps (4m x 2n), warp tile 64x64. 4-stage cp.async pipeline, BK=32.
__device__ __forceinline__ void mma_unit(
    const __nv_bfloat16* __restrict__ A,
    const __nv_bfloat16* __restrict__ W,
    float* __restrict__ C, int ldC,
    int m0, int n0, uint32_t smem0)
{
    const int tid  = threadIdx.x;
    const int lane = tid & 31;
    const int wid  = tid >> 5;
    const int wm   = (wid & 3) * 64;   // warp m-slab
    const int wn   = (wid >> 2) * 64;  // warp n-slab

    // ---- per-thread cp.async mapping: i 0..3 -> A segs, 4..5 -> W segs ----
    const char* baseA = (const char*)(A + (size_t)m0 * Kd);
    const char* baseW = (const char*)(W + (size_t)n0 * Kd);
    uint32_t s_off[6], g_off[6];
    #pragma unroll
    for (int i = 0; i < 6; i++) {
        int seg = tid + i * 256;
        if (i < 4) {                      // A: 256 rows x 4 x 16B
            int row = seg >> 2, part = seg & 3;
            s_off[i] = row * PITCH + part * 16;
            g_off[i] = row * (Kd * 2) + part * 16;
        } else {                          // W: 128 rows x 4 x 16B
            int s2 = seg - 1024;
            int row = s2 >> 2, part = s2 & 3;
            s_off[i] = BM * PITCH + row * PITCH + part * 16;
            g_off[i] = row * (Kd * 2) + part * 16;
        }
    }

    float acc[4][8][4];
    #pragma unroll
    for (int mi = 0; mi < 4; mi++)
        #pragma unroll
        for (int ni = 0; ni < 8; ni++)
            #pragma unroll
            for (int q = 0; q < 4; q++) acc[mi][ni][q] = 0.f;

    // ldmatrix lane address components (non-trans for both operands)
    const int a_r = (lane & 7) + (lane & 8);          // m row within 16
    const int a_k = (lane >> 4) * 16;                 // +0 / +16 bytes
    const int b_r = (lane & 7) + ((lane >> 4) << 3);  // n row within 16
    const int b_k = (lane & 8) ? 16 : 0;              // +0 / +16 bytes

    auto issue = [&](int c) {
        uint32_t st = smem0 + (c & 3) * STAGE_BYTES;
        uint32_t gadd = (uint32_t)c * 64;   // 32 bf16 = 64 bytes per chunk
        #pragma unroll
        for (int i = 0; i < 4; i++) cpa16s(st + s_off[i], baseA + g_off[i] + gadd);
        #pragma unroll
        for (int i = 4; i < 6; i++) cpa16s(st + s_off[i], baseW + g_off[i] + gadd);
        cpa_commit();
    };
    issue(0); issue(1); issue(2);

    #pragma unroll 1
    for (int c = 0; c < 32; c++) {
        if (c < 30) cpa_wait<2>(); else if (c == 30) cpa_wait<1>(); else cpa_wait<0>();
        __syncthreads();
        uint32_t st = smem0 + (c & 3) * STAGE_BYTES;
        uint32_t sB = st + BM * PITCH;
        #pragma unroll
        for (int ks = 0; ks < 2; ks++) {
            uint32_t a4[4][4], b4[4][4];
            #pragma unroll
            for (int mi = 0; mi < 4; mi++)
                ldsm_x4(a4[mi], st + (wm + mi * 16 + a_r) * PITCH + a_k + ks * 32);
            #pragma unroll
            for (int bi = 0; bi < 4; bi++)
                ldsm_x4(b4[bi], sB + (wn + bi * 16 + b_r) * PITCH + b_k + ks * 32);
            #pragma unroll
            for (int mi = 0; mi < 4; mi++)
                #pragma unroll
                for (int bi = 0; bi < 4; bi++) {
                    mma16816(acc[mi][2 * bi],     a4[mi], b4[bi][0], b4[bi][1]);
                    mma16816(acc[mi][2 * bi + 1], a4[mi], b4[bi][2], b4[bi][3]);
                }
        }
        if (c + 3 < 32) issue(c + 3);
    }

    // epilogue: acc frag (m16n8 f32): c0,c1 @ (lane>>2, 2*(lane&3)); c2,c3 @ +8 rows
    const int er = lane >> 2;
    const int ec = (lane & 3) * 2;
    #pragma unroll
    for (int mi = 0; mi < 4; mi++) {
        #pragma unroll
        for (int ni = 0; ni < 8; ni++) {
            float* p = C + (size_t)(m0 + wm + mi * 16 + er) * ldC + n0 + wn + ni * 8 + ec;
            *(float2*)p             = make_float2(acc[mi][ni][0], acc[mi][ni][1]);
            *(float2*)(p + 8 * ldC) = make_float2(acc[mi][ni][2], acc[mi][ni][3]);
        }
    }
    __syncthreads();
}

// ---------------- phase helpers ----------------
__device__ __forceinline__ float sigmoidf_(float x) { return 1.f / (1.f + __expf(-x)); }

__device__ __forceinline__ void gate_phase(
    const float* __restrict__ gi, const float* __restrict__ gh,
    const float* __restrict__ bi, const float* __restrict__ bh,
    float* __restrict__ h, __nv_bfloat16* __restrict__ hb)
{
    for (int idx = blockIdx.x * blockDim.x + threadIdx.x;
         idx < Bsz * Hsz; idx += gridDim.x * blockDim.x) {
        int b = idx >> 10, j = idx & 1023;
        const float* gib = gi + (size_t)b * G3;
        const float* ghb = gh + (size_t)b * G3;
        float r  = sigmoidf_(gib[j]        + bi[j]        + ghb[j]        + bh[j]);
        float z  = sigmoidf_(gib[1024 + j] + bi[1024 + j] + ghb[1024 + j] + bh[1024 + j]);
        float n  = tanhf(gib[2048 + j] + bi[2048 + j] + r * (ghb[2048 + j] + bh[2048 + j]));
        float hv = (1.f - z) * n + z * h[idx];
        h[idx]  = hv;
        hb[idx] = __float2bfloat16(hv);
    }
}

__device__ __forceinline__ void logprob_phase(
    int t, const int* __restrict__ target, const float* __restrict__ b_out,
    float* __restrict__ lp, float* red)
{
    for (int b = blockIdx.x; b < Bsz; b += gridDim.x) {
        const float* row = g_logits + (size_t)b * Vpad;
        int tid = threadIdx.x;
        float m = -1e30f;
        for (int v = tid; v < Vsz; v += 256) m = fmaxf(m, row[v] + b_out[v]);
        red[tid] = m; __syncthreads();
        for (int s = 128; s; s >>= 1) { if (tid < s) red[tid] = fmaxf(red[tid], red[tid + s]); __syncthreads(); }
        float mx = red[0]; __syncthreads();
        float sacc = 0.f;
        for (int v = tid; v < Vsz; v += 256) sacc += __expf(row[v] + b_out[v] - mx);
        red[tid] = sacc; __syncthreads();
        for (int s = 128; s; s >>= 1) { if (tid < s) red[tid] += red[tid + s]; __syncthreads(); }
        if (tid == 0) {
            int tg = target[b * Tsz + t];
            lp[b] += row[tg] + b_out[tg] - (mx + __logf(red[0]));
        }
        __syncthreads();
    }
}

// ---------------- persistent wavefront kernel ----------------
// Super-step s GEMM phase (all independent):
//   gh1(t=s), gi2+gh2(t=s-1), gi3+gh3(t=s-2), logits(t=s-3)  -> 123 tile units
// Gate phase: gate1(s), gate2(s-1), gate3(s-2), logprob(s-3). 2 barriers/step.
__global__ __launch_bounds__(256, 1) void recur_kernel(
    const int* __restrict__ target,
    const float* __restrict__ b_ih1, const float* __restrict__ b_hh1,
    const float* __restrict__ b_ih2, const float* __restrict__ b_hh2,
    const float* __restrict__ b_ih3, const float* __restrict__ b_hh3,
    const float* __restrict__ b_out,
    float* __restrict__ lp)
{
    extern __shared__ char dsm[];
    __shared__ float red[256];
    const uint32_t smem0 = (smem_u32(dsm) + 127u) & ~127u;
    unsigned gen = 0;
    const int u = blockIdx.x;

    for (int s = 0; s < Tsz + 3; s++) {
        // ---- GEMM phase ----
        if (u < 24) {
            if (s < Tsz)
                mma_unit(g_h1b, g_wb + 1 * (size_t)WSEG, g_gh1, G3, 0, u * 128, smem0);
        } else if (u < 48) {
            if (s >= 1 && s <= Tsz)
                mma_unit(g_h1b, g_wb + 2 * (size_t)WSEG, g_gi2, G3, 0, (u - 24) * 128, smem0);
        } else if (u < 72) {
            if (s >= 1 && s <= Tsz)
                mma_unit(g_h2b, g_wb + 3 * (size_t)WSEG, g_gh2, G3, 0, (u - 48) * 128, smem0);
        } else if (u < 96) {
            if (s >= 2 && s <= Tsz + 1)
                mma_unit(g_h2b, g_wb + 4 * (size_t)WSEG, g_gi3, G3, 0, (u - 72) * 128, smem0);
        } else if (u < 120) {
            if (s >= 2 && s <= Tsz + 1)
                mma_unit(g_h3b, g_wb + 5 * (size_t)WSEG, g_gh3, G3, 0, (u - 96) * 128, smem0);
        } else if (u < 123) {
            if (s >= 3)
                mma_unit(g_h3b, g_wout, g_logits, Vpad, 0, (u - 120) * 128, smem0);
        }
        grid_barrier(gen);

        // ---- gate phase ----
        if (s < Tsz)
            gate_phase(g_gi1 + (size_t)s * Bsz * G3, g_gh1, b_ih1, b_hh1, g_h1, g_h1b);
        if (s >= 1 && s <= Tsz)
            gate_phase(g_gi2, g_gh2, b_ih2, b_hh2, g_h2, g_h2b);
        if (s >= 2 && s <= Tsz + 1)
            gate_phase(g_gi3, g_gh3, b_ih3, b_hh3, g_h3, g_h3b);
        if (s >= 3)
            logprob_phase(s - 3, target, b_out, lp, red);
        grid_barrier(gen);
    }
}

// ---------------- gi1 pre-GEMM (parallel over all timesteps) ----------------
__global__ __launch_bounds__(256, 1) void gemm_gi1_kernel() {
    extern __shared__ char dsm[];
    const uint32_t smem0 = (smem_u32(dsm) + 127u) & ~127u;
    mma_unit(g_xb, g_wb /* w_ih1 */, g_gi1, G3,
             blockIdx.y * BM, blockIdx.x * BN, smem0);
}

// ---------------- setup kernels ----------------
__global__ __launch_bounds__(256) void init_state(float* lp) {
    for (int i = blockIdx.x * blockDim.x + threadIdx.x;
         i < Bsz * Hsz; i += gridDim.x * blockDim.x) {
        g_h1[i] = 0.f; g_h2[i] = 0.f; g_h3[i] = 0.f;
        __nv_bfloat16 z = __float2bfloat16(0.f);
        g_h1b[i] = z; g_h2b[i] = z; g_h3b[i] = z;
        if (i < Bsz) lp[i] = 0.f;
        if (i == 0) { g_bar_count = 0u; g_bar_gen = 0u; }
    }
}

__global__ __launch_bounds__(256) void conv_weights(
    const float* __restrict__ w0, const float* __restrict__ w1,
    const float* __restrict__ w2, const float* __restrict__ w3,
    const float* __restrict__ w4, const float* __restrict__ w5)
{
    for (size_t i = (size_t)blockIdx.x * blockDim.x + threadIdx.x;
         i < 6 * (size_t)WSEG; i += (size_t)gridDim.x * blockDim.x) {
        int seg = (int)(i / WSEG);
        size_t off = i % WSEG;
        const float* s = seg == 0 ? w0 : seg == 1 ? w1 : seg == 2 ? w2
                       : seg == 3 ? w3 : seg == 4 ? w4 : w5;
        g_wb[i] = __float2bfloat16(s[off]);
    }
}

__global__ __launch_bounds__(256) void conv_wout(const float* __restrict__ w_out) {
    for (int i = blockIdx.x * blockDim.x + threadIdx.x;
         i < Vpad * Kd; i += gridDim.x * blockDim.x) {
        int row = i >> 10;
        g_wout[i] = (row < Vsz) ? __float2bfloat16(w_out[i]) : __float2bfloat16(0.f);
    }
}

__global__ __launch_bounds__(256) void gather_x(
    const int* __restrict__ target, const int* __restrict__ bosp,
    const float* __restrict__ emb)
{
    const int nq = Tsz * Bsz * (Kd / 4);
    for (int i = blockIdx.x * blockDim.x + threadIdx.x; i < nq; i += gridDim.x * blockDim.x) {
        int m  = i / (Kd / 4);
        int kq = i % (Kd / 4);
        int t = m >> 8, b = m & 255;
        int tok = (t == 0) ? bosp[0] : target[(b << 7) + t - 1];
        float4 v = *(const float4*)(emb + (size_t)tok * Kd + kq * 4);
        __nv_bfloat16* dst = g_xb + (size_t)m * Kd + kq * 4;
        *(__nv_bfloat162*)(dst)     = __floats2bfloat162_rn(v.x, v.y);
        *(__nv_bfloat162*)(dst + 2) = __floats2bfloat162_rn(v.z, v.w);
    }
}

// ---------------- launch ----------------
extern "C" void kernel_launch(void* const* d_in, const int* in_sizes, int n_in,
                              void* d_out, int out_size)
{
    (void)in_sizes; (void)n_in; (void)out_size;
    const int*   target = (const int*)  d_in[0];
    const int*   bos    = (const int*)  d_in[1];
    const float* emb    = (const float*)d_in[2];
    const float* w_ih1  = (const float*)d_in[3];
    const float* w_hh1  = (const float*)d_in[4];
    const float* b_ih1  = (const float*)d_in[5];
    const float* b_hh1  = (const float*)d_in[6];
    const float* w_ih2  = (const float*)d_in[7];
    const float* w_hh2  = (const float*)d_in[8];
    const float* b_ih2  = (const float*)d_in[9];
    const float* b_hh2  = (const float*)d_in[10];
    const float* w_ih3  = (const float*)d_in[11];
    const float* w_hh3  = (const float*)d_in[12];
    const float* b_ih3  = (const float*)d_in[13];
    const float* b_hh3  = (const float*)d_in[14];
    const float* w_out  = (const float*)d_in[15];
    const float* b_out  = (const float*)d_in[16];
    float* lp = (float*)d_out;

    cudaFuncSetAttribute(recur_kernel,
        cudaFuncAttributeMaxDynamicSharedMemorySize, SMEM_DYN);
    cudaFuncSetAttribute(gemm_gi1_kernel,
        cudaFuncAttributeMaxDynamicSharedMemorySize, SMEM_DYN);

    init_state<<<1024, 256>>>(lp);
    conv_weights<<<8192, 256>>>(w_ih1, w_hh1, w_ih2, w_hh2, w_ih3, w_hh3);
    conv_wout<<<(Vpad * Kd + 255) / 256, 256>>>(w_out);
    gather_x<<<8192, 256>>>(target, bos, emb);

    {
        dim3 grid(G3 / BN, (Tsz * Bsz) / BM);   // 24 x 128
        gemm_gi1_kernel<<<grid, 256, SMEM_DYN>>>();
    }

    recur_kernel<<<NBLK, 256, SMEM_DYN>>>(target,
                                b_ih1, b_hh1, b_ih2, b_hh2, b_ih3, b_hh3,
                                b_out, lp);
}

// round 7
// speedup vs baseline: 3.0364x; 1.0770x over previous
#include <cuda_runtime.h>
#include <cuda_bf16.h>
#include <math.h>
#include <stdint.h>

#define Bsz  256
#define Tsz  128
#define Hsz  1024
#define G3   3072
#define Vsz  348
#define Vpad 384
#define Kd   1024
#define NBLK 148
#define WSEG 3145728   // 3072*1024

// GEMM config: BM=256 (=full M), BN=128, BK=32, 256 threads, warp tile 64x64
#define BM 256
#define BN 128
#define PITCH 80                         // smem row pitch bytes (32 bf16 + pad)
#define STAGE_BYTES ((BM + BN) * PITCH)  // 30720
#define NSTAGE 4
#define SMEM_DYN (NSTAGE * STAGE_BYTES + 256)

// ---------------- scratch (device globals; no allocs allowed) ----------------
__device__ float          g_gi1[(size_t)Tsz * Bsz * G3];
__device__ __nv_bfloat16  g_xb[(size_t)Tsz * Bsz * Kd];
__device__ __nv_bfloat16  g_wb[6 * (size_t)WSEG];
__device__ __nv_bfloat16  g_wout[Vpad * Kd];
__device__ float          g_gh1[Bsz * G3];
__device__ float          g_gi2[Bsz * G3], g_gh2[Bsz * G3];
__device__ float          g_gi3[Bsz * G3], g_gh3[Bsz * G3];
__device__ float          g_h1[Bsz * Hsz], g_h2[Bsz * Hsz], g_h3[Bsz * Hsz];
__device__ __nv_bfloat16  g_h1b[Bsz * Hsz], g_h2b[Bsz * Hsz], g_h3b[Bsz * Hsz];
__device__ float          g_logits[Bsz * Vpad];
__device__ unsigned       g_bar_count;   // monotonic
__device__ unsigned       g_bar_gen;     // monotonic

namespace {
struct Boot {
    Boot() { void* p = nullptr; cudaGetSymbolAddress(&p, g_gi1); }
};
static Boot boot_;
}

// ---------------- low-level helpers ----------------
__device__ __forceinline__ uint32_t smem_u32(const void* p) {
    return (uint32_t)__cvta_generic_to_shared(p);
}
__device__ __forceinline__ void cpa16s(uint32_t saddr, const void* g) {
    asm volatile("cp.async.cg.shared.global [%0], [%1], 16;" :: "r"(saddr), "l"(g));
}
__device__ __forceinline__ void cpa_commit() {
    asm volatile("cp.async.commit_group;");
}
template <int N>
__device__ __forceinline__ void cpa_wait() {
    asm volatile("cp.async.wait_group %0;" :: "n"(N));
}
__device__ __forceinline__ void ldsm_x4(uint32_t* r, uint32_t a) {
    asm volatile("ldmatrix.sync.aligned.m8n8.x4.shared.b16 {%0,%1,%2,%3}, [%4];"
        : "=r"(r[0]), "=r"(r[1]), "=r"(r[2]), "=r"(r[3]) : "r"(a));
}
__device__ __forceinline__ void mma16816(float* c, const uint32_t* a, uint32_t b0, uint32_t b1) {
    asm volatile(
        "mma.sync.aligned.m16n8k16.row.col.f32.bf16.bf16.f32 "
        "{%0,%1,%2,%3},{%4,%5,%6,%7},{%8,%9},{%0,%1,%2,%3};"
        : "+f"(c[0]), "+f"(c[1]), "+f"(c[2]), "+f"(c[3])
        : "r"(a[0]), "r"(a[1]), "r"(a[2]), "r"(a[3]), "r"(b0), "r"(b1));
}

// ---------------- grid barrier (release/acquire, monotonic) ----------------
__device__ __forceinline__ void grid_barrier(unsigned& gen) {
    __syncthreads();
    if (threadIdx.x == 0) {
        unsigned target = gen + 1;
        unsigned old;
        asm volatile("atom.add.acq_rel.gpu.u32 %0, [%1], 1;"
                     : "=r"(old) : "l"(&g_bar_count) : "memory");
        if (old == target * NBLK - 1) {
            asm volatile("st.release.gpu.u32 [%0], %1;"
                         :: "l"(&g_bar_gen), "r"(target) : "memory");
        } else {
            unsigned cur;
            do {
                asm volatile("ld.acquire.gpu.u32 %0, [%1];"
                             : "=r"(cur) : "l"(&g_bar_gen) : "memory");
            } while (cur < target);
        }
    }
    gen++;
    __syncthreads();
}

// ---------------- mma.sync GEMM unit: C[256 x 128] = A[256xK] @ W[128xK]^T ----------------
// A bf16 [M][K] row-major; W bf16 [N][K] row-major (= B col-major for mma.row.col).
// 256 threads = 8 warps (4m x 2n), warp tile 64x64. 4-stage cp.async pipeline, BK=32.
__device__ __forceinline__ void mma_unit(
    const __nv_bfloat16* __restrict__ A,
    const __nv_bfloat16* __restrict__ W,
    float* __restrict__ C, int ldC,
    int m0, int n0, uint32_t smem0)
{
    const int tid  = threadIdx.x;
    const int lane = tid & 31;
    const int wid  = tid >> 5;
    const int wm   = (wid & 3) * 64;   // warp m-slab
    const int wn   = (wid >> 2) * 64;  // warp n-slab

    // ---- per-thread cp.async mapping: i 0..3 -> A segs, 4..5 -> W segs ----
    const char* baseA = (const char*)(A + (size_t)m0 * Kd);
    const char* baseW = (const char*)(W + (size_t)n0 * Kd);
    uint32_t s_off[6], g_off[6];
    #pragma unroll
    for (int i = 0; i < 6; i++) {
        int seg = tid + i * 256;
        if (i < 4) {                      // A: 256 rows x 4 x 16B
            int row = seg >> 2, part = seg & 3;
            s_off[i] = row * PITCH + part * 16;
            g_off[i] = row * (Kd * 2) + part * 16;
        } else {                          // W: 128 rows x 4 x 16B
            int s2 = seg - 1024;
            int row = s2 >> 2, part = s2 & 3;
            s_off[i] = BM * PITCH + row * PITCH + part * 16;
            g_off[i] = row * (Kd * 2) + part * 16;
        }
    }

    float acc[4][8][4];
    #pragma unroll
    for (int mi = 0; mi < 4; mi++)
        #pragma unroll
        for (int ni = 0; ni < 8; ni++)
            #pragma unroll
            for (int q = 0; q < 4; q++) acc[mi][ni][q] = 0.f;

    // ldmatrix lane address components (non-trans for both operands)
    const int a_r = (lane & 7) + (lane & 8);          // m row within 16
    const int a_k = (lane >> 4) * 16;                 // +0 / +16 bytes
    const int b_r = (lane & 7) + ((lane >> 4) << 3);  // n row within 16
    const int b_k = (lane & 8) ? 16 : 0;              // +0 / +16 bytes

    auto issue = [&](int c) {
        uint32_t st = smem0 + (c & 3) * STAGE_BYTES;
        uint32_t gadd = (uint32_t)c * 64;   // 32 bf16 = 64 bytes per chunk
        #pragma unroll
        for (int i = 0; i < 4; i++) cpa16s(st + s_off[i], baseA + g_off[i] + gadd);
        #pragma unroll
        for (int i = 4; i < 6; i++) cpa16s(st + s_off[i], baseW + g_off[i] + gadd);
        cpa_commit();
    };
    issue(0); issue(1); issue(2);

    #pragma unroll 1
    for (int c = 0; c < 32; c++) {
        if (c < 30) cpa_wait<2>(); else if (c == 30) cpa_wait<1>(); else cpa_wait<0>();
        __syncthreads();
        // refill the pipeline BEFORE compute: stage (c+3)&3 was last read in
        // chunk c-1 (fully consumed before the __syncthreads above).
        if (c + 3 < 32) issue(c + 3);
        uint32_t st = smem0 + (c & 3) * STAGE_BYTES;
        uint32_t sB = st + BM * PITCH;
        #pragma unroll
        for (int ks = 0; ks < 2; ks++) {
            uint32_t a4[4][4], b4[4][4];
            #pragma unroll
            for (int mi = 0; mi < 4; mi++)
                ldsm_x4(a4[mi], st + (wm + mi * 16 + a_r) * PITCH + a_k + ks * 32);
            #pragma unroll
            for (int bi = 0; bi < 4; bi++)
                ldsm_x4(b4[bi], sB + (wn + bi * 16 + b_r) * PITCH + b_k + ks * 32);
            #pragma unroll
            for (int mi = 0; mi < 4; mi++)
                #pragma unroll
                for (int bi = 0; bi < 4; bi++) {
                    mma16816(acc[mi][2 * bi],     a4[mi], b4[bi][0], b4[bi][1]);
                    mma16816(acc[mi][2 * bi + 1], a4[mi], b4[bi][2], b4[bi][3]);
                }
        }
    }

    // epilogue: acc frag (m16n8 f32): c0,c1 @ (lane>>2, 2*(lane&3)); c2,c3 @ +8 rows
    const int er = lane >> 2;
    const int ec = (lane & 3) * 2;
    #pragma unroll
    for (int mi = 0; mi < 4; mi++) {
        #pragma unroll
        for (int ni = 0; ni < 8; ni++) {
            float* p = C + (size_t)(m0 + wm + mi * 16 + er) * ldC + n0 + wn + ni * 8 + ec;
            *(float2*)p             = make_float2(acc[mi][ni][0], acc[mi][ni][1]);
            *(float2*)(p + 8 * ldC) = make_float2(acc[mi][ni][2], acc[mi][ni][3]);
        }
    }
    __syncthreads();
}

// ---------------- phase helpers ----------------
__device__ __forceinline__ float sigmoidf_(float x) { return 1.f / (1.f + __expf(-x)); }

__device__ __forceinline__ void gate_phase(
    const float* __restrict__ gi, const float* __restrict__ gh,
    const float* __restrict__ bi, const float* __restrict__ bh,
    float* __restrict__ h, __nv_bfloat16* __restrict__ hb)
{
    for (int idx = blockIdx.x * blockDim.x + threadIdx.x;
         idx < Bsz * Hsz; idx += gridDim.x * blockDim.x) {
        int b = idx >> 10, j = idx & 1023;
        const float* gib = gi + (size_t)b * G3;
        const float* ghb = gh + (size_t)b * G3;
        float r  = sigmoidf_(gib[j]        + bi[j]        + ghb[j]        + bh[j]);
        float z  = sigmoidf_(gib[1024 + j] + bi[1024 + j] + ghb[1024 + j] + bh[1024 + j]);
        float n  = tanhf(gib[2048 + j] + bi[2048 + j] + r * (ghb[2048 + j] + bh[2048 + j]));
        float hv = (1.f - z) * n + z * h[idx];
        h[idx]  = hv;
        hb[idx] = __float2bfloat16(hv);
    }
}

__device__ __forceinline__ void logprob_phase(
    int t, const int* __restrict__ target, const float* __restrict__ b_out,
    float* __restrict__ lp, float* red)
{
    for (int b = blockIdx.x; b < Bsz; b += gridDim.x) {
        const float* row = g_logits + (size_t)b * Vpad;
        int tid = threadIdx.x;
        float m = -1e30f;
        for (int v = tid; v < Vsz; v += 256) m = fmaxf(m, row[v] + b_out[v]);
        red[tid] = m; __syncthreads();
        for (int s = 128; s; s >>= 1) { if (tid < s) red[tid] = fmaxf(red[tid], red[tid + s]); __syncthreads(); }
        float mx = red[0]; __syncthreads();
        float sacc = 0.f;
        for (int v = tid; v < Vsz; v += 256) sacc += __expf(row[v] + b_out[v] - mx);
        red[tid] = sacc; __syncthreads();
        for (int s = 128; s; s >>= 1) { if (tid < s) red[tid] += red[tid + s]; __syncthreads(); }
        if (tid == 0) {
            int tg = target[b * Tsz + t];
            lp[b] += row[tg] + b_out[tg] - (mx + __logf(red[0]));
        }
        __syncthreads();
    }
}

// ---------------- persistent wavefront kernel ----------------
// Super-step s GEMM phase (all independent; 147 of 148 blocks busy):
//   gh1(t=s), gi2+gh2(t=s-1), gi3+gh3(t=s-2), logits(t=s-3), gi1(t=s+1)
// Gate phase: gate1(s), gate2(s-1), gate3(s-2), logprob(s-3). 2 barriers/step.
// Loop s = -1 .. 130: s=-1 computes only gi1(0).
__global__ __launch_bounds__(256, 1) void recur_kernel(
    const int* __restrict__ target,
    const float* __restrict__ b_ih1, const float* __restrict__ b_hh1,
    const float* __restrict__ b_ih2, const float* __restrict__ b_hh2,
    const float* __restrict__ b_ih3, const float* __restrict__ b_hh3,
    const float* __restrict__ b_out,
    float* __restrict__ lp)
{
    extern __shared__ char dsm[];
    __shared__ float red[256];
    const uint32_t smem0 = (smem_u32(dsm) + 127u) & ~127u;
    unsigned gen = 0;
    const int u = blockIdx.x;

    for (int s = -1; s < Tsz + 3; s++) {
        // ---- GEMM phase ----
        if (u < 24) {
            if (s >= 0 && s < Tsz)
                mma_unit(g_h1b, g_wb + 1 * (size_t)WSEG, g_gh1, G3, 0, u * 128, smem0);
        } else if (u < 48) {
            if (s >= 1 && s <= Tsz)
                mma_unit(g_h1b, g_wb + 2 * (size_t)WSEG, g_gi2, G3, 0, (u - 24) * 128, smem0);
        } else if (u < 72) {
            if (s >= 1 && s <= Tsz)
                mma_unit(g_h2b, g_wb + 3 * (size_t)WSEG, g_gh2, G3, 0, (u - 48) * 128, smem0);
        } else if (u < 96) {
            if (s >= 2 && s <= Tsz + 1)
                mma_unit(g_h2b, g_wb + 4 * (size_t)WSEG, g_gi3, G3, 0, (u - 72) * 128, smem0);
        } else if (u < 120) {
            if (s >= 2 && s <= Tsz + 1)
                mma_unit(g_h3b, g_wb + 5 * (size_t)WSEG, g_gh3, G3, 0, (u - 96) * 128, smem0);
        } else if (u < 123) {
            if (s >= 3)
                mma_unit(g_h3b, g_wout, g_logits, Vpad, 0, (u - 120) * 128, smem0);
        } else if (u < 147) {
            int tg1 = s + 1;                   // gi1 for the NEXT super-step
            if (tg1 >= 0 && tg1 < Tsz)
                mma_unit(g_xb + (size_t)tg1 * Bsz * Kd, g_wb /* w_ih1 */,
                         g_gi1 + (size_t)tg1 * Bsz * G3, G3, 0, (u - 123) * 128, smem0);
        }
        grid_barrier(gen);

        // ---- gate phase ----
        if (s >= 0 && s < Tsz)
            gate_phase(g_gi1 + (size_t)s * Bsz * G3, g_gh1, b_ih1, b_hh1, g_h1, g_h1b);
        if (s >= 1 && s <= Tsz)
            gate_phase(g_gi2, g_gh2, b_ih2, b_hh2, g_h2, g_h2b);
        if (s >= 2 && s <= Tsz + 1)
            gate_phase(g_gi3, g_gh3, b_ih3, b_hh3, g_h3, g_h3b);
        if (s >= 3)
            logprob_phase(s - 3, target, b_out, lp, red);
        grid_barrier(gen);
    }
}

// ---------------- setup kernels (merged to 3 launches before recur) ----------------
__global__ __launch_bounds__(256) void init_misc(const float* __restrict__ w_out,
                                                 float* __restrict__ lp)
{
    // zero states + lp + barrier, and convert/pad w_out
    for (int i = blockIdx.x * blockDim.x + threadIdx.x;
         i < Vpad * Kd; i += gridDim.x * blockDim.x) {
        int row = i >> 10;
        g_wout[i] = (row < Vsz) ? __float2bfloat16(w_out[i]) : __float2bfloat16(0.f);
        if (i < Bsz * Hsz) {
            g_h1[i] = 0.f; g_h2[i] = 0.f; g_h3[i] = 0.f;
            __nv_bfloat16 z = __float2bfloat16(0.f);
            g_h1b[i] = z; g_h2b[i] = z; g_h3b[i] = z;
        }
        if (i < Bsz) lp[i] = 0.f;
        if (i == 0) { g_bar_count = 0u; g_bar_gen = 0u; }
    }
}

__global__ __launch_bounds__(256) void conv_weights(
    const float* __restrict__ w0, const float* __restrict__ w1,
    const float* __restrict__ w2, const float* __restrict__ w3,
    const float* __restrict__ w4, const float* __restrict__ w5)
{
    for (size_t i = (size_t)blockIdx.x * blockDim.x + threadIdx.x;
         i < 6 * (size_t)WSEG; i += (size_t)gridDim.x * blockDim.x) {
        int seg = (int)(i / WSEG);
        size_t off = i % WSEG;
        const float* s = seg == 0 ? w0 : seg == 1 ? w1 : seg == 2 ? w2
                       : seg == 3 ? w3 : seg == 4 ? w4 : w5;
        g_wb[i] = __float2bfloat16(s[off]);
    }
}

__global__ __launch_bounds__(256) void gather_x(
    const int* __restrict__ target, const int* __restrict__ bosp,
    const float* __restrict__ emb)
{
    const int nq = Tsz * Bsz * (Kd / 4);
    for (int i = blockIdx.x * blockDim.x + threadIdx.x; i < nq; i += gridDim.x * blockDim.x) {
        int m  = i / (Kd / 4);
        int kq = i % (Kd / 4);
        int t = m >> 8, b = m & 255;
        int tok = (t == 0) ? bosp[0] : target[(b << 7) + t - 1];
        float4 v = *(const float4*)(emb + (size_t)tok * Kd + kq * 4);
        __nv_bfloat16* dst = g_xb + (size_t)m * Kd + kq * 4;
        *(__nv_bfloat162*)(dst)     = __floats2bfloat162_rn(v.x, v.y);
        *(__nv_bfloat162*)(dst + 2) = __floats2bfloat162_rn(v.z, v.w);
    }
}

// ---------------- launch ----------------
extern "C" void kernel_launch(void* const* d_in, const int* in_sizes, int n_in,
                              void* d_out, int out_size)
{
    (void)in_sizes; (void)n_in; (void)out_size;
    const int*   target = (const int*)  d_in[0];
    const int*   bos    = (const int*)  d_in[1];
    const float* emb    = (const float*)d_in[2];
    const float* w_ih1  = (const float*)d_in[3];
    const float* w_hh1  = (const float*)d_in[4];
    const float* b_ih1  = (const float*)d_in[5];
    const float* b_hh1  = (const float*)d_in[6];
    const float* w_ih2  = (const float*)d_in[7];
    const float* w_hh2  = (const float*)d_in[8];
    const float* b_ih2  = (const float*)d_in[9];
    const float* b_hh2  = (const float*)d_in[10];
    const float* w_ih3  = (const float*)d_in[11];
    const float* w_hh3  = (const float*)d_in[12];
    const float* b_ih3  = (const float*)d_in[13];
    const float* b_hh3  = (const float*)d_in[14];
    const float* w_out  = (const float*)d_in[15];
    const float* b_out  = (const float*)d_in[16];
    float* lp = (float*)d_out;

    cudaFuncSetAttribute(recur_kernel,
        cudaFuncAttributeMaxDynamicSharedMemorySize, SMEM_DYN);

    init_misc<<<(Vpad * Kd + 255) / 256, 256>>>(w_out, lp);
    conv_weights<<<8192, 256>>>(w_ih1, w_hh1, w_ih2, w_hh2, w_ih3, w_hh3);
    gather_x<<<8192, 256>>>(target, bos, emb);

    recur_kernel<<<NBLK, 256, SMEM_DYN>>>(target,
                                b_ih1, b_hh1, b_ih2, b_hh2, b_ih3, b_hh3,
                                b_out, lp);
}

// round 8
// speedup vs baseline: 3.3937x; 1.1177x over previous
#include <cuda_runtime.h>
#include <cuda_bf16.h>
#include <math.h>
#include <stdint.h>

#define Bsz  256
#define Tsz  128
#define Hsz  1024
#define G3   3072
#define Vsz  348
#define Vpad 384
#define Kd   1024
#define NBLK 148
#define NTHR 512
#define WSEG 3145728   // 3072*1024

// GEMM config: BM=256 (=full M), BN=128, BK=32, 512 threads, warp tile 64x32
#define BM 256
#define BN 128
#define PITCH 80                         // smem row pitch bytes (32 bf16 + pad)
#define STAGE_BYTES ((BM + BN) * PITCH)  // 30720
#define NSTAGE 4
#define SMEM_DYN (NSTAGE * STAGE_BYTES + 256)

// ---------------- scratch (device globals; no allocs allowed) ----------------
__device__ float          g_gi1[(size_t)Tsz * Bsz * G3];
__device__ __nv_bfloat16  g_xb[(size_t)Tsz * Bsz * Kd];
__device__ __nv_bfloat16  g_wb[6 * (size_t)WSEG];
__device__ __nv_bfloat16  g_wout[Vpad * Kd];
__device__ float          g_gh1[Bsz * G3];
__device__ float          g_gi2[Bsz * G3], g_gh2[Bsz * G3];
__device__ float          g_gi3[Bsz * G3], g_gh3[Bsz * G3];
__device__ float          g_h1[Bsz * Hsz], g_h2[Bsz * Hsz], g_h3[Bsz * Hsz];
__device__ __nv_bfloat16  g_h1b[Bsz * Hsz], g_h2b[Bsz * Hsz], g_h3b[Bsz * Hsz];
__device__ float          g_logits[Bsz * Vpad];
__device__ unsigned       g_bar_count;   // monotonic
__device__ unsigned       g_bar_gen;     // monotonic

namespace {
struct Boot {
    Boot() { void* p = nullptr; cudaGetSymbolAddress(&p, g_gi1); }
};
static Boot boot_;
}

// ---------------- low-level helpers ----------------
__device__ __forceinline__ uint32_t smem_u32(const void* p) {
    return (uint32_t)__cvta_generic_to_shared(p);
}
__device__ __forceinline__ void cpa16s(uint32_t saddr, const void* g) {
    asm volatile("cp.async.cg.shared.global [%0], [%1], 16;" :: "r"(saddr), "l"(g));
}
__device__ __forceinline__ void cpa_commit() {
    asm volatile("cp.async.commit_group;");
}
template <int N>
__device__ __forceinline__ void cpa_wait() {
    asm volatile("cp.async.wait_group %0;" :: "n"(N));
}
__device__ __forceinline__ void ldsm_x4(uint32_t* r, uint32_t a) {
    asm volatile("ldmatrix.sync.aligned.m8n8.x4.shared.b16 {%0,%1,%2,%3}, [%4];"
        : "=r"(r[0]), "=r"(r[1]), "=r"(r[2]), "=r"(r[3]) : "r"(a));
}
__device__ __forceinline__ void mma16816(float* c, const uint32_t* a, uint32_t b0, uint32_t b1) {
    asm volatile(
        "mma.sync.aligned.m16n8k16.row.col.f32.bf16.bf16.f32 "
        "{%0,%1,%2,%3},{%4,%5,%6,%7},{%8,%9},{%0,%1,%2,%3};"
        : "+f"(c[0]), "+f"(c[1]), "+f"(c[2]), "+f"(c[3])
        : "r"(a[0]), "r"(a[1]), "r"(a[2]), "r"(a[3]), "r"(b0), "r"(b1));
}

// ---------------- grid barrier (release/acquire, monotonic) ----------------
__device__ __forceinline__ void grid_barrier(unsigned& gen) {
    __syncthreads();
    if (threadIdx.x == 0) {
        unsigned target = gen + 1;
        unsigned old;
        asm volatile("atom.add.acq_rel.gpu.u32 %0, [%1], 1;"
                     : "=r"(old) : "l"(&g_bar_count) : "memory");
        if (old == target * NBLK - 1) {
            asm volatile("st.release.gpu.u32 [%0], %1;"
                         :: "l"(&g_bar_gen), "r"(target) : "memory");
        } else {
            unsigned cur;
            do {
                asm volatile("ld.acquire.gpu.u32 %0, [%1];"
                             : "=r"(cur) : "l"(&g_bar_gen) : "memory");
            } while (cur < target);
        }
    }
    gen++;
    __syncthreads();
}

// ---------------- mma.sync GEMM unit: C[256 x 128] = A[256xK] @ W[128xK]^T ----------------
// A bf16 [M][K] row-major; W bf16 [N][K] row-major (= B col-major for mma.row.col).
// 512 threads = 16 warps (4m x 4n), warp tile 64x32. 4-stage cp.async pipeline, BK=32.
__device__ __forceinline__ void mma_unit(
    const __nv_bfloat16* __restrict__ A,
    const __nv_bfloat16* __restrict__ W,
    float* __restrict__ C, int ldC,
    int m0, int n0, uint32_t smem0)
{
    const int tid  = threadIdx.x;
    const int lane = tid & 31;
    const int wid  = tid >> 5;          // 0..15
    const int wm   = (wid & 3) * 64;    // warp m-slab
    const int wn   = (wid >> 2) * 32;   // warp n-slab

    // ---- per-thread cp.async mapping: i 0..1 -> A segs, i 2 -> W seg ----
    const char* baseA = (const char*)(A + (size_t)m0 * Kd);
    const char* baseW = (const char*)(W + (size_t)n0 * Kd);
    uint32_t s_off[3], g_off[3];
    #pragma unroll
    for (int i = 0; i < 2; i++) {        // A: 256 rows x 4 x 16B = 1024 segs
        int seg = tid + i * NTHR;
        int row = seg >> 2, part = seg & 3;
        s_off[i] = row * PITCH + part * 16;
        g_off[i] = row * (Kd * 2) + part * 16;
    }
    {                                    // W: 128 rows x 4 x 16B = 512 segs
        int row = tid >> 2, part = tid & 3;
        s_off[2] = BM * PITCH + row * PITCH + part * 16;
        g_off[2] = row * (Kd * 2) + part * 16;
    }

    float acc[4][4][4];
    #pragma unroll
    for (int mi = 0; mi < 4; mi++)
        #pragma unroll
        for (int ni = 0; ni < 4; ni++)
            #pragma unroll
            for (int q = 0; q < 4; q++) acc[mi][ni][q] = 0.f;

    // ldmatrix lane address components (non-trans for both operands)
    const int a_r = (lane & 7) + (lane & 8);          // m row within 16
    const int a_k = (lane >> 4) * 16;                 // +0 / +16 bytes
    const int b_r = (lane & 7) + ((lane >> 4) << 3);  // n row within 16
    const int b_k = (lane & 8) ? 16 : 0;              // +0 / +16 bytes

    auto issue = [&](int c) {
        uint32_t st = smem0 + (c & 3) * STAGE_BYTES;
        uint32_t gadd = (uint32_t)c * 64;   // 32 bf16 = 64 bytes per chunk
        cpa16s(st + s_off[0], baseA + g_off[0] + gadd);
        cpa16s(st + s_off[1], baseA + g_off[1] + gadd);
        cpa16s(st + s_off[2], baseW + g_off[2] + gadd);
        cpa_commit();
    };
    issue(0); issue(1); issue(2);

    #pragma unroll 1
    for (int c = 0; c < 32; c++) {
        if (c < 30) cpa_wait<2>(); else if (c == 30) cpa_wait<1>(); else cpa_wait<0>();
        __syncthreads();
        // refill the pipeline BEFORE compute: stage (c+3)&3 was last read in
        // chunk c-1 (fully consumed before the __syncthreads above).
        if (c + 3 < 32) issue(c + 3);
        uint32_t st = smem0 + (c & 3) * STAGE_BYTES;
        uint32_t sB = st + BM * PITCH;
        #pragma unroll
        for (int ks = 0; ks < 2; ks++) {
            uint32_t a4[4][4], b4[2][4];
            #pragma unroll
            for (int mi = 0; mi < 4; mi++)
                ldsm_x4(a4[mi], st + (wm + mi * 16 + a_r) * PITCH + a_k + ks * 32);
            #pragma unroll
            for (int bi = 0; bi < 2; bi++)
                ldsm_x4(b4[bi], sB + (wn + bi * 16 + b_r) * PITCH + b_k + ks * 32);
            #pragma unroll
            for (int mi = 0; mi < 4; mi++)
                #pragma unroll
                for (int bi = 0; bi < 2; bi++) {
                    mma16816(acc[mi][2 * bi],     a4[mi], b4[bi][0], b4[bi][1]);
                    mma16816(acc[mi][2 * bi + 1], a4[mi], b4[bi][2], b4[bi][3]);
                }
        }
    }

    // epilogue: acc frag (m16n8 f32): c0,c1 @ (lane>>2, 2*(lane&3)); c2,c3 @ +8 rows
    const int er = lane >> 2;
    const int ec = (lane & 3) * 2;
    #pragma unroll
    for (int mi = 0; mi < 4; mi++) {
        #pragma unroll
        for (int ni = 0; ni < 4; ni++) {
            float* p = C + (size_t)(m0 + wm + mi * 16 + er) * ldC + n0 + wn + ni * 8 + ec;
            *(float2*)p             = make_float2(acc[mi][ni][0], acc[mi][ni][1]);
            *(float2*)(p + 8 * ldC) = make_float2(acc[mi][ni][2], acc[mi][ni][3]);
        }
    }
    __syncthreads();
}

// ---------------- phase helpers ----------------
__device__ __forceinline__ float sigmoidf_(float x) { return 1.f / (1.f + __expf(-x)); }

__device__ __forceinline__ void gate_phase(
    const float* __restrict__ gi, const float* __restrict__ gh,
    const float* __restrict__ bi, const float* __restrict__ bh,
    float* __restrict__ h, __nv_bfloat16* __restrict__ hb)
{
    for (int idx = blockIdx.x * blockDim.x + threadIdx.x;
         idx < Bsz * Hsz; idx += gridDim.x * blockDim.x) {
        int b = idx >> 10, j = idx & 1023;
        const float* gib = gi + (size_t)b * G3;
        const float* ghb = gh + (size_t)b * G3;
        float r  = sigmoidf_(gib[j]        + bi[j]        + ghb[j]        + bh[j]);
        float z  = sigmoidf_(gib[1024 + j] + bi[1024 + j] + ghb[1024 + j] + bh[1024 + j]);
        float n  = tanhf(gib[2048 + j] + bi[2048 + j] + r * (ghb[2048 + j] + bh[2048 + j]));
        float hv = (1.f - z) * n + z * h[idx];
        h[idx]  = hv;
        hb[idx] = __float2bfloat16(hv);
    }
}

__device__ __forceinline__ void logprob_phase(
    int t, const int* __restrict__ target, const float* __restrict__ b_out,
    float* __restrict__ lp, float* red)
{
    for (int b = blockIdx.x; b < Bsz; b += gridDim.x) {
        const float* row = g_logits + (size_t)b * Vpad;
        int tid = threadIdx.x;
        float m = -1e30f;
        for (int v = tid; v < Vsz; v += NTHR) m = fmaxf(m, row[v] + b_out[v]);
        red[tid] = m; __syncthreads();
        for (int s = NTHR / 2; s; s >>= 1) { if (tid < s) red[tid] = fmaxf(red[tid], red[tid + s]); __syncthreads(); }
        float mx = red[0]; __syncthreads();
        float sacc = 0.f;
        for (int v = tid; v < Vsz; v += NTHR) sacc += __expf(row[v] + b_out[v] - mx);
        red[tid] = sacc; __syncthreads();
        for (int s = NTHR / 2; s; s >>= 1) { if (tid < s) red[tid] += red[tid + s]; __syncthreads(); }
        if (tid == 0) {
            int tg = target[b * Tsz + t];
            lp[b] += row[tg] + b_out[tg] - (mx + __logf(red[0]));
        }
        __syncthreads();
    }
}

// ---------------- persistent wavefront kernel ----------------
// Super-step s GEMM phase (all independent; 147 of 148 blocks busy):
//   gh1(t=s), gi2+gh2(t=s-1), gi3+gh3(t=s-2), logits(t=s-3), gi1(t=s+1)
// Gate phase: gate1(s), gate2(s-1), gate3(s-2), logprob(s-3). 2 barriers/step.
// Loop s = -1 .. 130: s=-1 computes only gi1(0).
__global__ __launch_bounds__(NTHR, 1) void recur_kernel(
    const int* __restrict__ target,
    const float* __restrict__ b_ih1, const float* __restrict__ b_hh1,
    const float* __restrict__ b_ih2, const float* __restrict__ b_hh2,
    const float* __restrict__ b_ih3, const float* __restrict__ b_hh3,
    const float* __restrict__ b_out,
    float* __restrict__ lp)
{
    extern __shared__ char dsm[];
    __shared__ float red[NTHR];
    const uint32_t smem0 = (smem_u32(dsm) + 127u) & ~127u;
    unsigned gen = 0;
    const int u = blockIdx.x;

    for (int s = -1; s < Tsz + 3; s++) {
        // ---- GEMM phase ----
        if (u < 24) {
            if (s >= 0 && s < Tsz)
                mma_unit(g_h1b, g_wb + 1 * (size_t)WSEG, g_gh1, G3, 0, u * 128, smem0);
        } else if (u < 48) {
            if (s >= 1 && s <= Tsz)
                mma_unit(g_h1b, g_wb + 2 * (size_t)WSEG, g_gi2, G3, 0, (u - 24) * 128, smem0);
        } else if (u < 72) {
            if (s >= 1 && s <= Tsz)
                mma_unit(g_h2b, g_wb + 3 * (size_t)WSEG, g_gh2, G3, 0, (u - 48) * 128, smem0);
        } else if (u < 96) {
            if (s >= 2 && s <= Tsz + 1)
                mma_unit(g_h2b, g_wb + 4 * (size_t)WSEG, g_gi3, G3, 0, (u - 72) * 128, smem0);
        } else if (u < 120) {
            if (s >= 2 && s <= Tsz + 1)
                mma_unit(g_h3b, g_wb + 5 * (size_t)WSEG, g_gh3, G3, 0, (u - 96) * 128, smem0);
        } else if (u < 123) {
            if (s >= 3)
                mma_unit(g_h3b, g_wout, g_logits, Vpad, 0, (u - 120) * 128, smem0);
        } else if (u < 147) {
            int tg1 = s + 1;                   // gi1 for the NEXT super-step
            if (tg1 >= 0 && tg1 < Tsz)
                mma_unit(g_xb + (size_t)tg1 * Bsz * Kd, g_wb /* w_ih1 */,
                         g_gi1 + (size_t)tg1 * Bsz * G3, G3, 0, (u - 123) * 128, smem0);
        }
        grid_barrier(gen);

        // ---- gate phase ----
        if (s >= 0 && s < Tsz)
            gate_phase(g_gi1 + (size_t)s * Bsz * G3, g_gh1, b_ih1, b_hh1, g_h1, g_h1b);
        if (s >= 1 && s <= Tsz)
            gate_phase(g_gi2, g_gh2, b_ih2, b_hh2, g_h2, g_h2b);
        if (s >= 2 && s <= Tsz + 1)
            gate_phase(g_gi3, g_gh3, b_ih3, b_hh3, g_h3, g_h3b);
        if (s >= 3)
            logprob_phase(s - 3, target, b_out, lp, red);
        grid_barrier(gen);
    }
}

// ---------------- setup kernels ----------------
__global__ __launch_bounds__(256) void init_misc(const float* __restrict__ w_out,
                                                 float* __restrict__ lp)
{
    for (int i = blockIdx.x * blockDim.x + threadIdx.x;
         i < Vpad * Kd; i += gridDim.x * blockDim.x) {
        int row = i >> 10;
        g_wout[i] = (row < Vsz) ? __float2bfloat16(w_out[i]) : __float2bfloat16(0.f);
        if (i < Bsz * Hsz) {
            g_h1[i] = 0.f; g_h2[i] = 0.f; g_h3[i] = 0.f;
            __nv_bfloat16 z = __float2bfloat16(0.f);
            g_h1b[i] = z; g_h2b[i] = z; g_h3b[i] = z;
        }
        if (i < Bsz) lp[i] = 0.f;
        if (i == 0) { g_bar_count = 0u; g_bar_gen = 0u; }
    }
}

__global__ __launch_bounds__(256) void conv_weights(
    const float* __restrict__ w0, const float* __restrict__ w1,
    const float* __restrict__ w2, const float* __restrict__ w3,
    const float* __restrict__ w4, const float* __restrict__ w5)
{
    for (size_t i = (size_t)blockIdx.x * blockDim.x + threadIdx.x;
         i < 6 * (size_t)WSEG; i += (size_t)gridDim.x * blockDim.x) {
        int seg = (int)(i / WSEG);
        size_t off = i % WSEG;
        const float* s = seg == 0 ? w0 : seg == 1 ? w1 : seg == 2 ? w2
                       : seg == 3 ? w3 : seg == 4 ? w4 : w5;
        g_wb[i] = __float2bfloat16(s[off]);
    }
}

__global__ __launch_bounds__(256) void gather_x(
    const int* __restrict__ target, const int* __restrict__ bosp,
    const float* __restrict__ emb)
{
    const int nq = Tsz * Bsz * (Kd / 4);
    for (int i = blockIdx.x * blockDim.x + threadIdx.x; i < nq; i += gridDim.x * blockDim.x) {
        int m  = i / (Kd / 4);
        int kq = i % (Kd / 4);
        int t = m >> 8, b = m & 255;
        int tok = (t == 0) ? bosp[0] : target[(b << 7) + t - 1];
        float4 v = *(const float4*)(emb + (size_t)tok * Kd + kq * 4);
        __nv_bfloat16* dst = g_xb + (size_t)m * Kd + kq * 4;
        *(__nv_bfloat162*)(dst)     = __floats2bfloat162_rn(v.x, v.y);
        *(__nv_bfloat162*)(dst + 2) = __floats2bfloat162_rn(v.z, v.w);
    }
}

// ---------------- launch ----------------
extern "C" void kernel_launch(void* const* d_in, const int* in_sizes, int n_in,
                              void* d_out, int out_size)
{
    (void)in_sizes; (void)n_in; (void)out_size;
    const int*   target = (const int*)  d_in[0];
    const int*   bos    = (const int*)  d_in[1];
    const float* emb    = (const float*)d_in[2];
    const float* w_ih1  = (const float*)d_in[3];
    const float* w_hh1  = (const float*)d_in[4];
    const float* b_ih1  = (const float*)d_in[5];
    const float* b_hh1  = (const float*)d_in[6];
    const float* w_ih2  = (const float*)d_in[7];
    const float* w_hh2  = (const float*)d_in[8];
    const float* b_ih2  = (const float*)d_in[9];
    const float* b_hh2  = (const float*)d_in[10];
    const float* w_ih3  = (const float*)d_in[11];
    const float* w_hh3  = (const float*)d_in[12];
    const float* b_ih3  = (const float*)d_in[13];
    const float* b_hh3  = (const float*)d_in[14];
    const float* w_out  = (const float*)d_in[15];
    const float* b_out  = (const float*)d_in[16];
    float* lp = (float*)d_out;

    cudaFuncSetAttribute(recur_kernel,
        cudaFuncAttributeMaxDynamicSharedMemorySize, SMEM_DYN);

    init_misc<<<(Vpad * Kd + 255) / 256, 256>>>(w_out, lp);
    conv_weights<<<8192, 256>>>(w_ih1, w_hh1, w_ih2, w_hh2, w_ih3, w_hh3);
    gather_x<<<8192, 256>>>(target, bos, emb);

    recur_kernel<<<NBLK, NTHR, SMEM_DYN>>>(target,
                                b_ih1, b_hh1, b_ih2, b_hh2, b_ih3, b_hh3,
                                b_out, lp);
}

// round 9
// speedup vs baseline: 3.5021x; 1.0319x over previous
#include <cuda_runtime.h>
#include <cuda_bf16.h>
#include <math.h>
#include <stdint.h>

#define Bsz  256
#define Tsz  128
#define Hsz  1024
#define G3   3072
#define Vsz  348
#define Vpad 384
#define Kd   1024
#define NBLK 148
#define NTHR 512
#define WSEG 3145728   // 3072*1024

// GEMM config: BM=256 (=full M), BN=128, BK=32, 512 threads, warp tile 64x32
// 6-stage cp.async ring, ONE __syncthreads per 64-K region (2 chunks).
#define BM 256
#define BN 128
#define PITCH 80                         // smem row pitch bytes (32 bf16 + pad)
#define STAGE_BYTES ((BM + BN) * PITCH)  // 30720
#define NSTAGE 6
#define SMEM_DYN (NSTAGE * STAGE_BYTES + 256)   // 184832

// ---------------- scratch (device globals; no allocs allowed) ----------------
__device__ float          g_gi1[(size_t)Tsz * Bsz * G3];
__device__ __nv_bfloat16  g_xb[(size_t)Tsz * Bsz * Kd];
__device__ __nv_bfloat16  g_wb[6 * (size_t)WSEG];
__device__ __nv_bfloat16  g_wout[Vpad * Kd];
__device__ float          g_gh1[Bsz * G3];
__device__ float          g_gi2[Bsz * G3], g_gh2[Bsz * G3];
__device__ float          g_gi3[Bsz * G3], g_gh3[Bsz * G3];
__device__ float          g_h1[Bsz * Hsz], g_h2[Bsz * Hsz], g_h3[Bsz * Hsz];
__device__ __nv_bfloat16  g_h1b[Bsz * Hsz], g_h2b[Bsz * Hsz], g_h3b[Bsz * Hsz];
__device__ float          g_logits[Bsz * Vpad];
__device__ unsigned       g_bar_count;   // monotonic
__device__ unsigned       g_bar_gen;     // monotonic

namespace {
struct Boot {
    Boot() { void* p = nullptr; cudaGetSymbolAddress(&p, g_gi1); }
};
static Boot boot_;
}

// ---------------- low-level helpers ----------------
__device__ __forceinline__ uint32_t smem_u32(const void* p) {
    return (uint32_t)__cvta_generic_to_shared(p);
}
__device__ __forceinline__ void cpa16s(uint32_t saddr, const void* g) {
    asm volatile("cp.async.cg.shared.global [%0], [%1], 16;" :: "r"(saddr), "l"(g));
}
__device__ __forceinline__ void cpa_commit() {
    asm volatile("cp.async.commit_group;");
}
template <int N>
__device__ __forceinline__ void cpa_wait() {
    asm volatile("cp.async.wait_group %0;" :: "n"(N));
}
__device__ __forceinline__ void ldsm_x4(uint32_t* r, uint32_t a) {
    asm volatile("ldmatrix.sync.aligned.m8n8.x4.shared.b16 {%0,%1,%2,%3}, [%4];"
        : "=r"(r[0]), "=r"(r[1]), "=r"(r[2]), "=r"(r[3]) : "r"(a));
}
__device__ __forceinline__ void mma16816(float* c, const uint32_t* a, uint32_t b0, uint32_t b1) {
    asm volatile(
        "mma.sync.aligned.m16n8k16.row.col.f32.bf16.bf16.f32 "
        "{%0,%1,%2,%3},{%4,%5,%6,%7},{%8,%9},{%0,%1,%2,%3};"
        : "+f"(c[0]), "+f"(c[1]), "+f"(c[2]), "+f"(c[3])
        : "r"(a[0]), "r"(a[1]), "r"(a[2]), "r"(a[3]), "r"(b0), "r"(b1));
}

// ---------------- grid barrier (release/acquire, monotonic) ----------------
__device__ __forceinline__ void grid_barrier(unsigned& gen) {
    __syncthreads();
    if (threadIdx.x == 0) {
        unsigned target = gen + 1;
        unsigned old;
        asm volatile("atom.add.acq_rel.gpu.u32 %0, [%1], 1;"
                     : "=r"(old) : "l"(&g_bar_count) : "memory");
        if (old == target * NBLK - 1) {
            asm volatile("st.release.gpu.u32 [%0], %1;"
                         :: "l"(&g_bar_gen), "r"(target) : "memory");
        } else {
            unsigned cur;
            do {
                asm volatile("ld.acquire.gpu.u32 %0, [%1];"
                             : "=r"(cur) : "l"(&g_bar_gen) : "memory");
            } while (cur < target);
        }
    }
    gen++;
    __syncthreads();
}

// ---------------- mma.sync GEMM unit: C[256 x 128] = A[256xK] @ W[128xK]^T ----------------
// A bf16 [M][K] row-major; W bf16 [N][K] row-major (= B col-major for mma.row.col).
// 512 threads = 16 warps (4m x 4n), warp tile 64x32.
// 6-stage cp.async ring; one __syncthreads per 64-K region (2 x BK=32 sub-chunks).
__device__ __forceinline__ void mma_unit(
    const __nv_bfloat16* __restrict__ A,
    const __nv_bfloat16* __restrict__ W,
    float* __restrict__ C, int ldC,
    int m0, int n0, uint32_t smem0)
{
    const int tid  = threadIdx.x;
    const int lane = tid & 31;
    const int wid  = tid >> 5;          // 0..15
    const int wm   = (wid & 3) * 64;    // warp m-slab
    const int wn   = (wid >> 2) * 32;   // warp n-slab

    // ---- per-thread cp.async mapping: i 0..1 -> A segs, i 2 -> W seg ----
    const char* baseA = (const char*)(A + (size_t)m0 * Kd);
    const char* baseW = (const char*)(W + (size_t)n0 * Kd);
    uint32_t s_off[3], g_off[3];
    #pragma unroll
    for (int i = 0; i < 2; i++) {        // A: 256 rows x 4 x 16B = 1024 segs
        int seg = tid + i * NTHR;
        int row = seg >> 2, part = seg & 3;
        s_off[i] = row * PITCH + part * 16;
        g_off[i] = row * (Kd * 2) + part * 16;
    }
    {                                    // W: 128 rows x 4 x 16B = 512 segs
        int row = tid >> 2, part = tid & 3;
        s_off[2] = BM * PITCH + row * PITCH + part * 16;
        g_off[2] = row * (Kd * 2) + part * 16;
    }

    float acc[4][4][4];
    #pragma unroll
    for (int mi = 0; mi < 4; mi++)
        #pragma unroll
        for (int ni = 0; ni < 4; ni++)
            #pragma unroll
            for (int q = 0; q < 4; q++) acc[mi][ni][q] = 0.f;

    // ldmatrix lane address components (non-trans for both operands)
    const int a_r = (lane & 7) + (lane & 8);          // m row within 16
    const int a_k = (lane >> 4) * 16;                 // +0 / +16 bytes
    const int b_r = (lane & 7) + ((lane >> 4) << 3);  // n row within 16
    const int b_k = (lane & 8) ? 16 : 0;              // +0 / +16 bytes

    auto issue = [&](int c) {
        uint32_t st = smem0 + (uint32_t)(c % NSTAGE) * STAGE_BYTES;
        uint32_t gadd = (uint32_t)c * 64;   // 32 bf16 = 64 bytes per chunk
        cpa16s(st + s_off[0], baseA + g_off[0] + gadd);
        cpa16s(st + s_off[1], baseA + g_off[1] + gadd);
        cpa16s(st + s_off[2], baseW + g_off[2] + gadd);
        cpa_commit();
    };
    issue(0); issue(1); issue(2); issue(3);

    #pragma unroll 1
    for (int cp = 0; cp < 16; cp++) {
        const int c0 = 2 * cp;
        // want sub-chunks c0, c0+1 complete; newest 2 groups may stay in flight
        if (cp < 15) cpa_wait<2>(); else cpa_wait<0>();
        __syncthreads();
        // refill: stages (c0+4)%6 and (c0+5)%6 are distinct from the two
        // stages read this region; their previous contents were consumed in
        // region cp-1 (drained by the __syncthreads above).
        if (c0 + 4 < 32) issue(c0 + 4);
        if (c0 + 5 < 32) issue(c0 + 5);
        #pragma unroll
        for (int h = 0; h < 2; h++) {
            uint32_t st = smem0 + (uint32_t)((c0 + h) % NSTAGE) * STAGE_BYTES;
            uint32_t sB = st + BM * PITCH;
            #pragma unroll
            for (int ks = 0; ks < 2; ks++) {
                uint32_t a4[4][4], b4[2][4];
                #pragma unroll
                for (int mi = 0; mi < 4; mi++)
                    ldsm_x4(a4[mi], st + (wm + mi * 16 + a_r) * PITCH + a_k + ks * 32);
                #pragma unroll
                for (int bi = 0; bi < 2; bi++)
                    ldsm_x4(b4[bi], sB + (wn + bi * 16 + b_r) * PITCH + b_k + ks * 32);
                #pragma unroll
                for (int mi = 0; mi < 4; mi++)
                    #pragma unroll
                    for (int bi = 0; bi < 2; bi++) {
                        mma16816(acc[mi][2 * bi],     a4[mi], b4[bi][0], b4[bi][1]);
                        mma16816(acc[mi][2 * bi + 1], a4[mi], b4[bi][2], b4[bi][3]);
                    }
            }
        }
    }

    // epilogue: acc frag (m16n8 f32): c0,c1 @ (lane>>2, 2*(lane&3)); c2,c3 @ +8 rows
    const int er = lane >> 2;
    const int ec = (lane & 3) * 2;
    #pragma unroll
    for (int mi = 0; mi < 4; mi++) {
        #pragma unroll
        for (int ni = 0; ni < 4; ni++) {
            float* p = C + (size_t)(m0 + wm + mi * 16 + er) * ldC + n0 + wn + ni * 8 + ec;
            *(float2*)p             = make_float2(acc[mi][ni][0], acc[mi][ni][1]);
            *(float2*)(p + 8 * ldC) = make_float2(acc[mi][ni][2], acc[mi][ni][3]);
        }
    }
    __syncthreads();
}

// ---------------- phase helpers ----------------
__device__ __forceinline__ float sigmoidf_(float x) { return 1.f / (1.f + __expf(-x)); }

__device__ __forceinline__ void gate_phase(
    const float* __restrict__ gi, const float* __restrict__ gh,
    const float* __restrict__ bi, const float* __restrict__ bh,
    float* __restrict__ h, __nv_bfloat16* __restrict__ hb)
{
    for (int idx = blockIdx.x * blockDim.x + threadIdx.x;
         idx < Bsz * Hsz; idx += gridDim.x * blockDim.x) {
        int b = idx >> 10, j = idx & 1023;
        const float* gib = gi + (size_t)b * G3;
        const float* ghb = gh + (size_t)b * G3;
        float r  = sigmoidf_(gib[j]        + bi[j]        + ghb[j]        + bh[j]);
        float z  = sigmoidf_(gib[1024 + j] + bi[1024 + j] + ghb[1024 + j] + bh[1024 + j]);
        float n  = tanhf(gib[2048 + j] + bi[2048 + j] + r * (ghb[2048 + j] + bh[2048 + j]));
        float hv = (1.f - z) * n + z * h[idx];
        h[idx]  = hv;
        hb[idx] = __float2bfloat16(hv);
    }
}

__device__ __forceinline__ void logprob_phase(
    int t, const int* __restrict__ target, const float* __restrict__ b_out,
    float* __restrict__ lp, float* red)
{
    for (int b = blockIdx.x; b < Bsz; b += gridDim.x) {
        const float* row = g_logits + (size_t)b * Vpad;
        int tid = threadIdx.x;
        float m = -1e30f;
        for (int v = tid; v < Vsz; v += NTHR) m = fmaxf(m, row[v] + b_out[v]);
        red[tid] = m; __syncthreads();
        for (int s = NTHR / 2; s; s >>= 1) { if (tid < s) red[tid] = fmaxf(red[tid], red[tid + s]); __syncthreads(); }
        float mx = red[0]; __syncthreads();
        float sacc = 0.f;
        for (int v = tid; v < Vsz; v += NTHR) sacc += __expf(row[v] + b_out[v] - mx);
        red[tid] = sacc; __syncthreads();
        for (int s = NTHR / 2; s; s >>= 1) { if (tid < s) red[tid] += red[tid + s]; __syncthreads(); }
        if (tid == 0) {
            int tg = target[b * Tsz + t];
            lp[b] += row[tg] + b_out[tg] - (mx + __logf(red[0]));
        }
        __syncthreads();
    }
}

// ---------------- persistent wavefront kernel ----------------
// Super-step s GEMM phase (all independent; 147 of 148 blocks busy):
//   gh1(t=s), gi2+gh2(t=s-1), gi3+gh3(t=s-2), logits(t=s-3), gi1(t=s+1)
// Gate phase: gate1(s), gate2(s-1), gate3(s-2), logprob(s-3). 2 barriers/step.
// Loop s = -1 .. 130: s=-1 computes only gi1(0).
__global__ __launch_bounds__(NTHR, 1) void recur_kernel(
    const int* __restrict__ target,
    const float* __restrict__ b_ih1, const float* __restrict__ b_hh1,
    const float* __restrict__ b_ih2, const float* __restrict__ b_hh2,
    const float* __restrict__ b_ih3, const float* __restrict__ b_hh3,
    const float* __restrict__ b_out,
    float* __restrict__ lp)
{
    extern __shared__ char dsm[];
    __shared__ float red[NTHR];
    const uint32_t smem0 = (smem_u32(dsm) + 127u) & ~127u;
    unsigned gen = 0;
    const int u = blockIdx.x;

    for (int s = -1; s < Tsz + 3; s++) {
        // ---- GEMM phase ----
        if (u < 24) {
            if (s >= 0 && s < Tsz)
                mma_unit(g_h1b, g_wb + 1 * (size_t)WSEG, g_gh1, G3, 0, u * 128, smem0);
        } else if (u < 48) {
            if (s >= 1 && s <= Tsz)
                mma_unit(g_h1b, g_wb + 2 * (size_t)WSEG, g_gi2, G3, 0, (u - 24) * 128, smem0);
        } else if (u < 72) {
            if (s >= 1 && s <= Tsz)
                mma_unit(g_h2b, g_wb + 3 * (size_t)WSEG, g_gh2, G3, 0, (u - 48) * 128, smem0);
        } else if (u < 96) {
            if (s >= 2 && s <= Tsz + 1)
                mma_unit(g_h2b, g_wb + 4 * (size_t)WSEG, g_gi3, G3, 0, (u - 72) * 128, smem0);
        } else if (u < 120) {
            if (s >= 2 && s <= Tsz + 1)
                mma_unit(g_h3b, g_wb + 5 * (size_t)WSEG, g_gh3, G3, 0, (u - 96) * 128, smem0);
        } else if (u < 123) {
            if (s >= 3)
                mma_unit(g_h3b, g_wout, g_logits, Vpad, 0, (u - 120) * 128, smem0);
        } else if (u < 147) {
            int tg1 = s + 1;                   // gi1 for the NEXT super-step
            if (tg1 >= 0 && tg1 < Tsz)
                mma_unit(g_xb + (size_t)tg1 * Bsz * Kd, g_wb /* w_ih1 */,
                         g_gi1 + (size_t)tg1 * Bsz * G3, G3, 0, (u - 123) * 128, smem0);
        }
        grid_barrier(gen);

        // ---- gate phase ----
        if (s >= 0 && s < Tsz)
            gate_phase(g_gi1 + (size_t)s * Bsz * G3, g_gh1, b_ih1, b_hh1, g_h1, g_h1b);
        if (s >= 1 && s <= Tsz)
            gate_phase(g_gi2, g_gh2, b_ih2, b_hh2, g_h2, g_h2b);
        if (s >= 2 && s <= Tsz + 1)
            gate_phase(g_gi3, g_gh3, b_ih3, b_hh3, g_h3, g_h3b);
        if (s >= 3)
            logprob_phase(s - 3, target, b_out, lp, red);
        grid_barrier(gen);
    }
}

// ---------------- setup kernels ----------------
__global__ __launch_bounds__(256) void init_misc(const float* __restrict__ w_out,
                                                 float* __restrict__ lp)
{
    for (int i = blockIdx.x * blockDim.x + threadIdx.x;
         i < Vpad * Kd; i += gridDim.x * blockDim.x) {
        int row = i >> 10;
        g_wout[i] = (row < Vsz) ? __float2bfloat16(w_out[i]) : __float2bfloat16(0.f);
        if (i < Bsz * Hsz) {
            g_h1[i] = 0.f; g_h2[i] = 0.f; g_h3[i] = 0.f;
            __nv_bfloat16 z = __float2bfloat16(0.f);
            g_h1b[i] = z; g_h2b[i] = z; g_h3b[i] = z;
        }
        if (i < Bsz) lp[i] = 0.f;
        if (i == 0) { g_bar_count = 0u; g_bar_gen = 0u; }
    }
}

__global__ __launch_bounds__(256) void conv_weights(
    const float* __restrict__ w0, const float* __restrict__ w1,
    const float* __restrict__ w2, const float* __restrict__ w3,
    const float* __restrict__ w4, const float* __restrict__ w5)
{
    for (size_t i = (size_t)blockIdx.x * blockDim.x + threadIdx.x;
         i < 6 * (size_t)WSEG; i += (size_t)gridDim.x * blockDim.x) {
        int seg = (int)(i / WSEG);
        size_t off = i % WSEG;
        const float* s = seg == 0 ? w0 : seg == 1 ? w1 : seg == 2 ? w2
                       : seg == 3 ? w3 : seg == 4 ? w4 : w5;
        g_wb[i] = __float2bfloat16(s[off]);
    }
}

__global__ __launch_bounds__(256) void gather_x(
    const int* __restrict__ target, const int* __restrict__ bosp,
    const float* __restrict__ emb)
{
    const int nq = Tsz * Bsz * (Kd / 4);
    for (int i = blockIdx.x * blockDim.x + threadIdx.x; i < nq; i += gridDim.x * blockDim.x) {
        int m  = i / (Kd / 4);
        int kq = i % (Kd / 4);
        int t = m >> 8, b = m & 255;
        int tok = (t == 0) ? bosp[0] : target[(b << 7) + t - 1];
        float4 v = *(const float4*)(emb + (size_t)tok * Kd + kq * 4);
        __nv_bfloat16* dst = g_xb + (size_t)m * Kd + kq * 4;
        *(__nv_bfloat162*)(dst)     = __floats2bfloat162_rn(v.x, v.y);
        *(__nv_bfloat162*)(dst + 2) = __floats2bfloat162_rn(v.z, v.w);
    }
}

// ---------------- launch ----------------
extern "C" void kernel_launch(void* const* d_in, const int* in_sizes, int n_in,
                              void* d_out, int out_size)
{
    (void)in_sizes; (void)n_in; (void)out_size;
    const int*   target = (const int*)  d_in[0];
    const int*   bos    = (const int*)  d_in[1];
    const float* emb    = (const float*)d_in[2];
    const float* w_ih1  = (const float*)d_in[3];
    const float* w_hh1  = (const float*)d_in[4];
    const float* b_ih1  = (const float*)d_in[5];
    const float* b_hh1  = (const float*)d_in[6];
    const float* w_ih2  = (const float*)d_in[7];
    const float* w_hh2  = (const float*)d_in[8];
    const float* b_ih2  = (const float*)d_in[9];
    const float* b_hh2  = (const float*)d_in[10];
    const float* w_ih3  = (const float*)d_in[11];
    const float* w_hh3  = (const float*)d_in[12];
    const float* b_ih3  = (const float*)d_in[13];
    const float* b_hh3  = (const float*)d_in[14];
    const float* w_out  = (const float*)d_in[15];
    const float* b_out  = (const float*)d_in[16];
    float* lp = (float*)d_out;

    cudaFuncSetAttribute(recur_kernel,
        cudaFuncAttributeMaxDynamicSharedMemorySize, SMEM_DYN);

    init_misc<<<(Vpad * Kd + 255) / 256, 256>>>(w_out, lp);
    conv_weights<<<8192, 256>>>(w_ih1, w_hh1, w_ih2, w_hh2, w_ih3, w_hh3);
    gather_x<<<8192, 256>>>(target, bos, emb);

    recur_kernel<<<NBLK, NTHR, SMEM_DYN>>>(target,
                                b_ih1, b_hh1, b_ih2, b_hh2, b_ih3, b_hh3,
                                b_out, lp);
}

// round 10
// speedup vs baseline: 4.2670x; 1.2184x over previous
#include <cuda_runtime.h>
#include <cuda_bf16.h>
#include <math.h>
#include <stdint.h>

#define Bsz  256
#define Tsz  128
#define Hsz  1024
#define G3   3072
#define Vsz  348
#define Vpad 384
#define Kd   1024
#define NBLK 148
#define NTHR 512
#define WSEG 3145728   // 3072*1024

// GEMM config: BM=256 (=full M), BN=128, BK=32, 512 threads, warp tile 64x32
// 6-stage cp.async ring, ONE __syncthreads per 64-K region (2 chunks).
#define BM 256
#define BN 128
#define PITCH 80                         // smem row pitch bytes (32 bf16 + pad)
#define STAGE_BYTES ((BM + BN) * PITCH)  // 30720
#define NSTAGE 6
#define SMEM_DYN (NSTAGE * STAGE_BYTES + 256)   // 184832

// ---------------- scratch (device globals; no allocs allowed) ----------------
__device__ __nv_bfloat16  g_gi1[(size_t)Tsz * Bsz * G3];   // bf16 now (201MB)
__device__ __nv_bfloat16  g_xb[(size_t)Tsz * Bsz * Kd];
__device__ __nv_bfloat16  g_wb[6 * (size_t)WSEG];
__device__ __nv_bfloat16  g_wout[Vpad * Kd];
__device__ __nv_bfloat16  g_gh1[Bsz * G3];
__device__ __nv_bfloat16  g_gi2[Bsz * G3], g_gh2[Bsz * G3];
__device__ __nv_bfloat16  g_gi3[Bsz * G3], g_gh3[Bsz * G3];
__device__ float          g_h1[Bsz * Hsz], g_h2[Bsz * Hsz], g_h3[Bsz * Hsz];
__device__ __nv_bfloat16  g_h1b[Bsz * Hsz], g_h2b[Bsz * Hsz], g_h3b[Bsz * Hsz];
__device__ float          g_logits[2 * Bsz * Vpad];        // double-buffered by step parity
__device__ unsigned       g_bar_count;   // monotonic
__device__ unsigned       g_bar_gen;     // monotonic

namespace {
struct Boot {
    Boot() { void* p = nullptr; cudaGetSymbolAddress(&p, g_gi1); }
};
static Boot boot_;
}

// ---------------- low-level helpers ----------------
__device__ __forceinline__ uint32_t smem_u32(const void* p) {
    return (uint32_t)__cvta_generic_to_shared(p);
}
__device__ __forceinline__ void cpa16s(uint32_t saddr, const void* g) {
    asm volatile("cp.async.cg.shared.global [%0], [%1], 16;" :: "r"(saddr), "l"(g));
}
__device__ __forceinline__ void cpa_commit() {
    asm volatile("cp.async.commit_group;");
}
template <int N>
__device__ __forceinline__ void cpa_wait() {
    asm volatile("cp.async.wait_group %0;" :: "n"(N));
}
__device__ __forceinline__ void ldsm_x4(uint32_t* r, uint32_t a) {
    asm volatile("ldmatrix.sync.aligned.m8n8.x4.shared.b16 {%0,%1,%2,%3}, [%4];"
        : "=r"(r[0]), "=r"(r[1]), "=r"(r[2]), "=r"(r[3]) : "r"(a));
}
__device__ __forceinline__ void mma16816(float* c, const uint32_t* a, uint32_t b0, uint32_t b1) {
    asm volatile(
        "mma.sync.aligned.m16n8k16.row.col.f32.bf16.bf16.f32 "
        "{%0,%1,%2,%3},{%4,%5,%6,%7},{%8,%9},{%0,%1,%2,%3};"
        : "+f"(c[0]), "+f"(c[1]), "+f"(c[2]), "+f"(c[3])
        : "r"(a[0]), "r"(a[1]), "r"(a[2]), "r"(a[3]), "r"(b0), "r"(b1));
}
// typed pair stores for the GEMM epilogue
__device__ __forceinline__ void store_pair(float* p, float a, float b) {
    *(float2*)p = make_float2(a, b);
}
__device__ __forceinline__ void store_pair(__nv_bfloat16* p, float a, float b) {
    *(__nv_bfloat162*)p = __floats2bfloat162_rn(a, b);
}
__device__ __forceinline__ float2 bf2(const __nv_bfloat16* p) {
    __nv_bfloat162 v = *(const __nv_bfloat162*)p;
    return make_float2(__bfloat162float(v.x), __bfloat162float(v.y));
}

// ---------------- grid barrier (release/acquire, monotonic) ----------------
__device__ __forceinline__ void grid_barrier(unsigned& gen) {
    __syncthreads();
    if (threadIdx.x == 0) {
        unsigned target = gen + 1;
        unsigned old;
        asm volatile("atom.add.acq_rel.gpu.u32 %0, [%1], 1;"
                     : "=r"(old) : "l"(&g_bar_count) : "memory");
        if (old == target * NBLK - 1) {
            asm volatile("st.release.gpu.u32 [%0], %1;"
                         :: "l"(&g_bar_gen), "r"(target) : "memory");
        } else {
            unsigned cur;
            do {
                asm volatile("ld.acquire.gpu.u32 %0, [%1];"
                             : "=r"(cur) : "l"(&g_bar_gen) : "memory");
            } while (cur < target);
        }
    }
    gen++;
    __syncthreads();
}

// ---------------- mma.sync GEMM unit: C[256 x 128] = A[256xK] @ W[128xK]^T ----------------
// A bf16 [M][K] row-major; W bf16 [N][K] row-major (= B col-major for mma.row.col).
// 512 threads = 16 warps (4m x 4n), warp tile 64x32.
// 6-stage cp.async ring; one __syncthreads per 64-K region (2 x BK=32 sub-chunks).
// C is float OR __nv_bfloat16 (template).
template <typename CT>
__device__ __forceinline__ void mma_unit(
    const __nv_bfloat16* __restrict__ A,
    const __nv_bfloat16* __restrict__ W,
    CT* __restrict__ C, int ldC,
    int m0, int n0, uint32_t smem0)
{
    const int tid  = threadIdx.x;
    const int lane = tid & 31;
    const int wid  = tid >> 5;          // 0..15
    const int wm   = (wid & 3) * 64;    // warp m-slab
    const int wn   = (wid >> 2) * 32;   // warp n-slab

    // ---- per-thread cp.async mapping: i 0..1 -> A segs, i 2 -> W seg ----
    const char* baseA = (const char*)(A + (size_t)m0 * Kd);
    const char* baseW = (const char*)(W + (size_t)n0 * Kd);
    uint32_t s_off[3], g_off[3];
    #pragma unroll
    for (int i = 0; i < 2; i++) {        // A: 256 rows x 4 x 16B = 1024 segs
        int seg = tid + i * NTHR;
        int row = seg >> 2, part = seg & 3;
        s_off[i] = row * PITCH + part * 16;
        g_off[i] = row * (Kd * 2) + part * 16;
    }
    {                                    // W: 128 rows x 4 x 16B = 512 segs
        int row = tid >> 2, part = tid & 3;
        s_off[2] = BM * PITCH + row * PITCH + part * 16;
        g_off[2] = row * (Kd * 2) + part * 16;
    }

    float acc[4][4][4];
    #pragma unroll
    for (int mi = 0; mi < 4; mi++)
        #pragma unroll
        for (int ni = 0; ni < 4; ni++)
            #pragma unroll
            for (int q = 0; q < 4; q++) acc[mi][ni][q] = 0.f;

    // ldmatrix lane address components (non-trans for both operands)
    const int a_r = (lane & 7) + (lane & 8);          // m row within 16
    const int a_k = (lane >> 4) * 16;                 // +0 / +16 bytes
    const int b_r = (lane & 7) + ((lane >> 4) << 3);  // n row within 16
    const int b_k = (lane & 8) ? 16 : 0;              // +0 / +16 bytes

    auto issue = [&](int c) {
        uint32_t st = smem0 + (uint32_t)(c % NSTAGE) * STAGE_BYTES;
        uint32_t gadd = (uint32_t)c * 64;   // 32 bf16 = 64 bytes per chunk
        cpa16s(st + s_off[0], baseA + g_off[0] + gadd);
        cpa16s(st + s_off[1], baseA + g_off[1] + gadd);
        cpa16s(st + s_off[2], baseW + g_off[2] + gadd);
        cpa_commit();
    };
    issue(0); issue(1); issue(2); issue(3);

    #pragma unroll 1
    for (int cp = 0; cp < 16; cp++) {
        const int c0 = 2 * cp;
        if (cp < 15) cpa_wait<2>(); else cpa_wait<0>();
        __syncthreads();
        if (c0 + 4 < 32) issue(c0 + 4);
        if (c0 + 5 < 32) issue(c0 + 5);
        #pragma unroll
        for (int h = 0; h < 2; h++) {
            uint32_t st = smem0 + (uint32_t)((c0 + h) % NSTAGE) * STAGE_BYTES;
            uint32_t sB = st + BM * PITCH;
            #pragma unroll
            for (int ks = 0; ks < 2; ks++) {
                uint32_t a4[4][4], b4[2][4];
                #pragma unroll
                for (int mi = 0; mi < 4; mi++)
                    ldsm_x4(a4[mi], st + (wm + mi * 16 + a_r) * PITCH + a_k + ks * 32);
                #pragma unroll
                for (int bi = 0; bi < 2; bi++)
                    ldsm_x4(b4[bi], sB + (wn + bi * 16 + b_r) * PITCH + b_k + ks * 32);
                #pragma unroll
                for (int mi = 0; mi < 4; mi++)
                    #pragma unroll
                    for (int bi = 0; bi < 2; bi++) {
                        mma16816(acc[mi][2 * bi],     a4[mi], b4[bi][0], b4[bi][1]);
                        mma16816(acc[mi][2 * bi + 1], a4[mi], b4[bi][2], b4[bi][3]);
                    }
            }
        }
    }

    // epilogue: acc frag (m16n8 f32): c0,c1 @ (lane>>2, 2*(lane&3)); c2,c3 @ +8 rows
    const int er = lane >> 2;
    const int ec = (lane & 3) * 2;
    #pragma unroll
    for (int mi = 0; mi < 4; mi++) {
        #pragma unroll
        for (int ni = 0; ni < 4; ni++) {
            CT* p = C + (size_t)(m0 + wm + mi * 16 + er) * ldC + n0 + wn + ni * 8 + ec;
            store_pair(p,            acc[mi][ni][0], acc[mi][ni][1]);
            store_pair(p + 8 * ldC,  acc[mi][ni][2], acc[mi][ni][3]);
        }
    }
    __syncthreads();
}

// ---------------- phase helpers ----------------
__device__ __forceinline__ float sigmoidf_(float x) { return 1.f / (1.f + __expf(-x)); }

// vectorized: 2 hidden units per iteration (bf16x2 / float2)
__device__ __forceinline__ void gate_phase(
    const __nv_bfloat16* __restrict__ gi, const __nv_bfloat16* __restrict__ gh,
    const float* __restrict__ bi, const float* __restrict__ bh,
    float* __restrict__ h, __nv_bfloat16* __restrict__ hb)
{
    const int NP = Bsz * Hsz / 2;
    for (int p = blockIdx.x * blockDim.x + threadIdx.x;
         p < NP; p += gridDim.x * blockDim.x) {
        int b = p >> 9;              // 512 pairs per batch row
        int j = (p & 511) * 2;
        const __nv_bfloat16* gib = gi + (size_t)b * G3;
        const __nv_bfloat16* ghb = gh + (size_t)b * G3;
        float2 ir = bf2(gib + j), iz = bf2(gib + 1024 + j), in2 = bf2(gib + 2048 + j);
        float2 hr = bf2(ghb + j), hz = bf2(ghb + 1024 + j), hn = bf2(ghb + 2048 + j);
        float2 br0 = *(const float2*)(bi + j), bz0 = *(const float2*)(bi + 1024 + j),
               bn0 = *(const float2*)(bi + 2048 + j);
        float2 br1 = *(const float2*)(bh + j), bz1 = *(const float2*)(bh + 1024 + j),
               bn1 = *(const float2*)(bh + 2048 + j);
        int idx = b * Hsz + j;
        float2 hp = *(const float2*)(h + idx);

        float r0 = sigmoidf_(ir.x + br0.x + hr.x + br1.x);
        float z0 = sigmoidf_(iz.x + bz0.x + hz.x + bz1.x);
        float n0 = tanhf(in2.x + bn0.x + r0 * (hn.x + bn1.x));
        float h0 = (1.f - z0) * n0 + z0 * hp.x;

        float r1 = sigmoidf_(ir.y + br0.y + hr.y + br1.y);
        float z1 = sigmoidf_(iz.y + bz0.y + hz.y + bz1.y);
        float n1 = tanhf(in2.y + bn0.y + r1 * (hn.y + bn1.y));
        float h1 = (1.f - z1) * n1 + z1 * hp.y;

        *(float2*)(h + idx) = make_float2(h0, h1);
        *(__nv_bfloat162*)(hb + idx) = __floats2bfloat162_rn(h0, h1);
    }
}

// warp-per-row logprob; runs in the GEMM phase on block 147 (no __syncthreads)
__device__ __forceinline__ void logprob_warp(
    int t, int par, const int* __restrict__ target,
    const float* __restrict__ b_out, float* __restrict__ lp)
{
    const int lane = threadIdx.x & 31;
    const int wid  = threadIdx.x >> 5;          // 0..15
    const float* L = g_logits + (size_t)par * Bsz * Vpad;
    for (int b = wid; b < Bsz; b += 16) {
        const float* row = L + (size_t)b * Vpad;
        float m = -1e30f;
        for (int v = lane; v < Vsz; v += 32) m = fmaxf(m, row[v] + b_out[v]);
        #pragma unroll
        for (int o = 16; o; o >>= 1) m = fmaxf(m, __shfl_xor_sync(0xffffffffu, m, o));
        float ss = 0.f;
        for (int v = lane; v < Vsz; v += 32) ss += __expf(row[v] + b_out[v] - m);
        #pragma unroll
        for (int o = 16; o; o >>= 1) ss += __shfl_xor_sync(0xffffffffu, ss, o);
        if (lane == 0) {
            int tg = target[b * Tsz + t];
            lp[b] += row[tg] + b_out[tg] - (m + __logf(ss));
        }
    }
}

// ---------------- persistent wavefront kernel ----------------
// Super-step s GEMM phase (all independent):
//   gh1(t=s), gi2+gh2(t=s-1), gi3+gh3(t=s-2), logits(t=s-3) -> parity s&1,
//   gi1(t=s+1), and block 147: logprob(t=s-4) from parity (s-1)&1.
// Gate phase: gate1(s), gate2(s-1), gate3(s-2). 2 barriers/step.
__global__ __launch_bounds__(NTHR, 1) void recur_kernel(
    const int* __restrict__ target,
    const float* __restrict__ b_ih1, const float* __restrict__ b_hh1,
    const float* __restrict__ b_ih2, const float* __restrict__ b_hh2,
    const float* __restrict__ b_ih3, const float* __restrict__ b_hh3,
    const float* __restrict__ b_out,
    float* __restrict__ lp)
{
    extern __shared__ char dsm[];
    const uint32_t smem0 = (smem_u32(dsm) + 127u) & ~127u;
    unsigned gen = 0;
    const int u = blockIdx.x;

    for (int s = -1; s < Tsz + 4; s++) {
        // ---- GEMM phase ----
        if (u < 24) {
            if (s >= 0 && s < Tsz)
                mma_unit(g_h1b, g_wb + 1 * (size_t)WSEG, g_gh1, G3, 0, u * 128, smem0);
        } else if (u < 48) {
            if (s >= 1 && s <= Tsz)
                mma_unit(g_h1b, g_wb + 2 * (size_t)WSEG, g_gi2, G3, 0, (u - 24) * 128, smem0);
        } else if (u < 72) {
            if (s >= 1 && s <= Tsz)
                mma_unit(g_h2b, g_wb + 3 * (size_t)WSEG, g_gh2, G3, 0, (u - 48) * 128, smem0);
        } else if (u < 96) {
            if (s >= 2 && s <= Tsz + 1)
                mma_unit(g_h2b, g_wb + 4 * (size_t)WSEG, g_gi3, G3, 0, (u - 72) * 128, smem0);
        } else if (u < 120) {
            if (s >= 2 && s <= Tsz + 1)
                mma_unit(g_h3b, g_wb + 5 * (size_t)WSEG, g_gh3, G3, 0, (u - 96) * 128, smem0);
        } else if (u < 123) {
            if (s >= 3 && s <= Tsz + 2)
                mma_unit(g_h3b, g_wout,
                         g_logits + (size_t)(s & 1) * Bsz * Vpad, Vpad,
                         0, (u - 120) * 128, smem0);
        } else if (u < 147) {
            int tg1 = s + 1;                   // gi1 for the NEXT super-step
            if (tg1 >= 0 && tg1 < Tsz)
                mma_unit(g_xb + (size_t)tg1 * Bsz * Kd, g_wb /* w_ih1 */,
                         g_gi1 + (size_t)tg1 * Bsz * G3, G3, 0, (u - 123) * 128, smem0);
        } else {
            if (s >= 4 && s <= Tsz + 3)
                logprob_warp(s - 4, (s - 1) & 1, target, b_out, lp);
        }
        grid_barrier(gen);

        // ---- gate phase ----
        if (s >= 0 && s < Tsz)
            gate_phase(g_gi1 + (size_t)s * Bsz * G3, g_gh1, b_ih1, b_hh1, g_h1, g_h1b);
        if (s >= 1 && s <= Tsz)
            gate_phase(g_gi2, g_gh2, b_ih2, b_hh2, g_h2, g_h2b);
        if (s >= 2 && s <= Tsz + 1)
            gate_phase(g_gi3, g_gh3, b_ih3, b_hh3, g_h3, g_h3b);
        grid_barrier(gen);
    }
}

// ---------------- setup kernels ----------------
__global__ __launch_bounds__(256) void init_misc(const float* __restrict__ w_out,
                                                 float* __restrict__ lp)
{
    for (int i = blockIdx.x * blockDim.x + threadIdx.x;
         i < Vpad * Kd; i += gridDim.x * blockDim.x) {
        int row = i >> 10;
        g_wout[i] = (row < Vsz) ? __float2bfloat16(w_out[i]) : __float2bfloat16(0.f);
        if (i < Bsz * Hsz) {
            g_h1[i] = 0.f; g_h2[i] = 0.f; g_h3[i] = 0.f;
            __nv_bfloat16 z = __float2bfloat16(0.f);
            g_h1b[i] = z; g_h2b[i] = z; g_h3b[i] = z;
        }
        if (i < Bsz) lp[i] = 0.f;
        if (i == 0) { g_bar_count = 0u; g_bar_gen = 0u; }
    }
}

__global__ __launch_bounds__(256) void conv_weights(
    const float* __restrict__ w0, const float* __restrict__ w1,
    const float* __restrict__ w2, const float* __restrict__ w3,
    const float* __restrict__ w4, const float* __restrict__ w5)
{
    for (size_t i = (size_t)blockIdx.x * blockDim.x + threadIdx.x;
         i < 6 * (size_t)WSEG; i += (size_t)gridDim.x * blockDim.x) {
        int seg = (int)(i / WSEG);
        size_t off = i % WSEG;
        const float* s = seg == 0 ? w0 : seg == 1 ? w1 : seg == 2 ? w2
                       : seg == 3 ? w3 : seg == 4 ? w4 : w5;
        g_wb[i] = __float2bfloat16(s[off]);
    }
}

__global__ __launch_bounds__(256) void gather_x(
    const int* __restrict__ target, const int* __restrict__ bosp,
    const float* __restrict__ emb)
{
    const int nq = Tsz * Bsz * (Kd / 4);
    for (int i = blockIdx.x * blockDim.x + threadIdx.x; i < nq; i += gridDim.x * blockDim.x) {
        int m  = i / (Kd / 4);
        int kq = i % (Kd / 4);
        int t = m >> 8, b = m & 255;
        int tok = (t == 0) ? bosp[0] : target[(b << 7) + t - 1];
        float4 v = *(const float4*)(emb + (size_t)tok * Kd + kq * 4);
        __nv_bfloat16* dst = g_xb + (size_t)m * Kd + kq * 4;
        *(__nv_bfloat162*)(dst)     = __floats2bfloat162_rn(v.x, v.y);
        *(__nv_bfloat162*)(dst + 2) = __floats2bfloat162_rn(v.z, v.w);
    }
}

// ---------------- launch ----------------
extern "C" void kernel_launch(void* const* d_in, const int* in_sizes, int n_in,
                              void* d_out, int out_size)
{
    (void)in_sizes; (void)n_in; (void)out_size;
    const int*   target = (const int*)  d_in[0];
    const int*   bos    = (const int*)  d_in[1];
    const float* emb    = (const float*)d_in[2];
    const float* w_ih1  = (const float*)d_in[3];
    const float* w_hh1  = (const float*)d_in[4];
    const float* b_ih1  = (const float*)d_in[5];
    const float* b_hh1  = (const float*)d_in[6];
    const float* w_ih2  = (const float*)d_in[7];
    const float* w_hh2  = (const float*)d_in[8];
    const float* b_ih2  = (const float*)d_in[9];
    const float* b_hh2  = (const float*)d_in[10];
    const float* w_ih3  = (const float*)d_in[11];
    const float* w_hh3  = (const float*)d_in[12];
    const float* b_ih3  = (const float*)d_in[13];
    const float* b_hh3  = (const float*)d_in[14];
    const float* w_out  = (const float*)d_in[15];
    const float* b_out  = (const float*)d_in[16];
    float* lp = (float*)d_out;

    cudaFuncSetAttribute(recur_kernel,
        cudaFuncAttributeMaxDynamicSharedMemorySize, SMEM_DYN);

    init_misc<<<(Vpad * Kd + 255) / 256, 256>>>(w_out, lp);
    conv_weights<<<8192, 256>>>(w_ih1, w_hh1, w_ih2, w_hh2, w_ih3, w_hh3);
    gather_x<<<8192, 256>>>(target, bos, emb);

    recur_kernel<<<NBLK, NTHR, SMEM_DYN>>>(target,
                                b_ih1, b_hh1, b_ih2, b_hh2, b_ih3, b_hh3,
                                b_out, lp);
}